// round 5
// baseline (speedup 1.0000x reference)
#include <cuda_runtime.h>
#include <math.h>

#define BB 4
#define NN 4096
#define KK 20
#define NPTS (BB*NN)            // 16384
#define EDG  (NPTS*KK)          // 327680
#define STATS_BLOCKS 512

#define FINF __int_as_float(0x7f800000)
#define ULLMAX 0xFFFFFFFFFFFFFFFFULL

// ---------------- scratch (device globals; no allocations allowed) ----------
__device__ unsigned g_distk[(size_t)BB * NN * NN];  // order-keys of distances (layer 1)
__device__ float4 g_x4[NPTS];                        // packed (x,y,z,|x|^2)
__device__ float g_d2[NPTS];
__device__ int   g_idx[NPTS * KK];
__device__ float g_u[NPTS * 256];
__device__ float g_v[NPTS * 256];
__device__ float g_vmax[NPTS * 256];
__device__ float g_vmin[NPTS * 256];
__device__ float g_h0[NPTS * 64];
__device__ float g_h1[NPTS * 256];
__device__ float g_Wd0[3 * 64];
__device__ float g_Wd1[64 * 256];
__device__ float g_part[STATS_BLOCKS * 2 * 256];
__device__ float g_scale[256];
__device__ float g_shift[256];
__device__ float g_gate[NPTS];
__device__ float g_alpha[NPTS];
__device__ float g_pool[32 * BB * 512];
__device__ float g_pooled[BB * 512];

static __device__ __forceinline__ float leaky(float v) { return v > 0.f ? v : 0.2f * v; }

// float -> order-preserving uint (ascending float == ascending uint)
static __device__ __forceinline__ unsigned okey(float f) {
    unsigned u = __float_as_uint(f);
    return u ^ ((unsigned)(((int)u) >> 31) | 0x80000000u);
}

// ---------------- weight prep: Wd = Wp - Wt ---------------------------------
__global__ void prep_k(const float* __restrict__ Wt0, const float* __restrict__ Wp0,
                       const float* __restrict__ Wt1, const float* __restrict__ Wp1) {
    int i = blockIdx.x * 256 + threadIdx.x;
    if (i < 192) g_Wd0[i] = Wp0[i] - Wt0[i];
    int j = i - 192;
    if (j >= 0 && j < 16384) g_Wd1[j] = Wp1[j] - Wt1[j];
}

// ---------------- pack x + squared norm --------------------------------------
__global__ void pack3_k(const float* __restrict__ x) {
    int r = blockIdx.x * blockDim.x + threadIdx.x;
    if (r >= NPTS) return;
    float a = x[r * 3], b = x[r * 3 + 1], c = x[r * 3 + 2];
    g_x4[r] = make_float4(a, b, c, a * a + b * b + c * c);
}

__global__ void norms64_k() {
    int gt = blockIdx.x * blockDim.x + threadIdx.x;
    int r = gt >> 5, lane = gt & 31;
    if (r >= NPTS) return;
    const float* h = g_h0 + (size_t)r * 64;
    float a = h[lane], b = h[lane + 32];
    float s = a * a + b * b;
    #pragma unroll
    for (int o = 16; o; o >>= 1) s += __shfl_down_sync(0xffffffffu, s, o);
    if (lane == 0) g_d2[r] = s;
}

// ---------------- layer0 u/v (3->64, trivial) --------------------------------
__global__ void uv0_k(const float* __restrict__ x, const float* __restrict__ Wt0) {
    int gid = blockIdx.x * 256 + threadIdx.x;   // NPTS*64 total
    int r = gid >> 6, c = gid & 63;
    float x0 = x[r * 3], x1 = x[r * 3 + 1], x2 = x[r * 3 + 2];
    g_u[gid] = x0 * Wt0[c] + x1 * Wt0[64 + c] + x2 * Wt0[128 + c];
    g_v[gid] = x0 * g_Wd0[c] + x1 * g_Wd0[64 + c] + x2 * g_Wd0[128 + c];
}

// ---------------- fused 16-row (64->256) GEMM: u1 = h0@Wt1, v1 = h0@Wd1 ------
__global__ __launch_bounds__(256) void gemm16_k(const float* __restrict__ Wt1) {
    __shared__ float hs[16 * 64];
    int r0 = blockIdx.x * 16;
    int t = threadIdx.x;
    #pragma unroll
    for (int s = 0; s < 4; s++) {
        int l = t + (s << 8);
        hs[l] = g_h0[(size_t)r0 * 64 + l];
    }
    __syncthreads();
    float au[16], av[16];
    #pragma unroll
    for (int r = 0; r < 16; r++) { au[r] = 0.f; av[r] = 0.f; }
    #pragma unroll 4
    for (int d = 0; d < 64; d++) {
        float wu = Wt1[d * 256 + t];
        float wv = g_Wd1[d * 256 + t];
        #pragma unroll
        for (int r = 0; r < 16; r++) {
            float h = hs[r * 64 + d];
            au[r] = fmaf(h, wu, au[r]);
            av[r] = fmaf(h, wv, av[r]);
        }
    }
    #pragma unroll
    for (int r = 0; r < 16; r++) {
        g_u[(size_t)(r0 + r) * 256 + t] = au[r];
        g_v[(size_t)(r0 + r) * 256 + t] = av[r];
    }
}

// ---------------- distance GEMM (layer1), triangular grid, key output --------
static __device__ __forceinline__ int tri_start(int ti) {
    return ti * 64 - (ti * (ti - 1)) / 2;
}

__global__ __launch_bounds__(256) void dist_gemm_k() {
    const int b = blockIdx.y;
    int l = blockIdx.x;                    // 0..2079
    int ti = (int)((129.0f - sqrtf(129.0f * 129.0f - 8.0f * (float)l)) * 0.5f);
    if (ti > 63) ti = 63;
    while (ti < 63 && tri_start(ti + 1) <= l) ti++;
    while (ti > 0 && tri_start(ti) > l) ti--;
    int tj = ti + (l - tri_start(ti));
    const int i0 = ti * 64, j0 = tj * 64;
    __shared__ float As[64][65];
    __shared__ float Bs[64][65];
    const float* hb = g_h0 + (size_t)b * NN * 64;
    int t = threadIdx.x;
    #pragma unroll
    for (int s = 0; s < 16; s++) {
        int ll = t + (s << 8);
        int r = ll >> 6, d = ll & 63;
        As[d][r] = hb[(size_t)(i0 + r) * 64 + d];
        Bs[d][r] = hb[(size_t)(j0 + r) * 64 + d];
    }
    __syncthreads();
    int tx = t & 15, ty = t >> 4;
    float acc[4][4];
    #pragma unroll
    for (int r = 0; r < 4; r++)
        #pragma unroll
        for (int c = 0; c < 4; c++) acc[r][c] = 0.f;
    #pragma unroll 8
    for (int d = 0; d < 64; d++) {
        float a0 = As[d][ty * 4 + 0], a1 = As[d][ty * 4 + 1];
        float a2 = As[d][ty * 4 + 2], a3 = As[d][ty * 4 + 3];
        float b0 = Bs[d][tx * 4 + 0], b1 = Bs[d][tx * 4 + 1];
        float b2 = Bs[d][tx * 4 + 2], b3 = Bs[d][tx * 4 + 3];
        acc[0][0] = fmaf(a0, b0, acc[0][0]); acc[0][1] = fmaf(a0, b1, acc[0][1]);
        acc[0][2] = fmaf(a0, b2, acc[0][2]); acc[0][3] = fmaf(a0, b3, acc[0][3]);
        acc[1][0] = fmaf(a1, b0, acc[1][0]); acc[1][1] = fmaf(a1, b1, acc[1][1]);
        acc[1][2] = fmaf(a1, b2, acc[1][2]); acc[1][3] = fmaf(a1, b3, acc[1][3]);
        acc[2][0] = fmaf(a2, b0, acc[2][0]); acc[2][1] = fmaf(a2, b1, acc[2][1]);
        acc[2][2] = fmaf(a2, b2, acc[2][2]); acc[2][3] = fmaf(a2, b3, acc[2][3]);
        acc[3][0] = fmaf(a3, b0, acc[3][0]); acc[3][1] = fmaf(a3, b1, acc[3][1]);
        acc[3][2] = fmaf(a3, b2, acc[3][2]); acc[3][3] = fmaf(a3, b3, acc[3][3]);
    }
    const float* n2 = g_d2 + b * NN;
    float nj0 = n2[j0 + tx * 4 + 0], nj1 = n2[j0 + tx * 4 + 1];
    float nj2 = n2[j0 + tx * 4 + 2], nj3 = n2[j0 + tx * 4 + 3];
    unsigned kv[4][4];
    #pragma unroll
    for (int r = 0; r < 4; r++) {
        float ni = n2[i0 + ty * 4 + r];
        kv[r][0] = okey(ni + nj0 - 2.f * acc[r][0]);
        kv[r][1] = okey(ni + nj1 - 2.f * acc[r][1]);
        kv[r][2] = okey(ni + nj2 - 2.f * acc[r][2]);
        kv[r][3] = okey(ni + nj3 - 2.f * acc[r][3]);
        *(uint4*)&g_distk[((size_t)(b * NN + i0 + ty * 4 + r)) * NN + j0 + tx * 4] =
            make_uint4(kv[r][0], kv[r][1], kv[r][2], kv[r][3]);
    }
    if (ti != tj) {
        __syncthreads();
        unsigned* Ts = (unsigned*)&As[0][0];   // reuse [64][65]
        #pragma unroll
        for (int r = 0; r < 4; r++)
            #pragma unroll
            for (int c = 0; c < 4; c++)
                Ts[(tx * 4 + c) * 65 + (ty * 4 + r)] = kv[r][c];
        __syncthreads();
        #pragma unroll
        for (int s = 0; s < 16; s++) {
            int ll = t + (s << 8);
            int jr = ll >> 6, ic = ll & 63;
            g_distk[((size_t)(b * NN + j0 + jr)) * NN + i0 + ic] = Ts[jr * 65 + ic];
        }
    }
}

// ---------------- register-resident hierarchical radix top-KK ----------------
// keys k[16] in registers, k[s] belongs to index j = t + s*256.
// smem: hist[2048], cand[256] u64, wsum[8], ctl[8].
__device__ __forceinline__ void select_reg(unsigned (&k)[16], unsigned* hist,
                                           unsigned long long* cand,
                                           int* wsum, int* ctl, int row) {
    const int t = threadIdx.x;
    const int lane = t & 31, w = t >> 5;
    int* out = g_idx + row * KK;
    int need = KK;
    unsigned pfx = 0;
    if (t == 0) ctl[0] = 0;

    for (int level = 0; level < 3; level++) {
        const int shift = (level == 0) ? 21 : (level == 1) ? 10 : 0;
        const unsigned bmask = (level == 2) ? 0x3FFu : 0x7FFu;
        // clear hist + collect counter
        #pragma unroll
        for (int i = 0; i < 8; i++) hist[t * 8 + i] = 0;
        if (t == 0) ctl[1] = 0;
        __syncthreads();
        // histogram active keys
        #pragma unroll
        for (int s = 0; s < 16; s++) {
            bool act = (level == 0) ? true
                     : (level == 1) ? ((k[s] >> 21) == pfx)
                                    : ((k[s] >> 10) == pfx);
            unsigned bal = __ballot_sync(0xffffffffu, act);
            if (act) {
                unsigned bin = (k[s] >> shift) & bmask;
                unsigned mm = __match_any_sync(bal, bin);
                if ((__ffs(mm) - 1) == lane) atomicAdd(&hist[bin], __popc(mm));
            }
        }
        __syncthreads();
        // inclusive scan over 2048 bins: per-thread 8 + block scan
        int lsum[8];
        int run = 0;
        #pragma unroll
        for (int i = 0; i < 8; i++) { run += (int)hist[t * 8 + i]; lsum[i] = run; }
        int inc = run;
        #pragma unroll
        for (int o = 1; o < 32; o <<= 1) {
            int n = __shfl_up_sync(0xffffffffu, inc, o);
            if (lane >= o) inc += n;
        }
        if (lane == 31) wsum[w] = inc;
        __syncthreads();
        if (t < 8) {
            int sv = wsum[t];
            #pragma unroll
            for (int o = 1; o < 8; o <<= 1) {
                int n = __shfl_up_sync(0xffu, sv, o);
                if (t >= o) sv += n;
            }
            wsum[t] = sv;
        }
        __syncthreads();
        int offs = (w ? wsum[w - 1] : 0) + (inc - run);
        #pragma unroll
        for (int i = 0; i < 8; i++) hist[t * 8 + i] = (unsigned)(lsum[i] + offs);
        __syncthreads();
        // find pivot bin
        #pragma unroll
        for (int i = 0; i < 8; i++) {
            int bin = t * 8 + i;
            int cum = (int)hist[bin];
            int prev = bin ? (int)hist[bin - 1] : 0;
            if (cum >= need && prev < need) { ctl[2] = bin; ctl[3] = need - prev; ctl[4] = cum - prev; }
        }
        __syncthreads();
        int B = ctl[2], nneed = ctl[3], cnt = ctl[4];
        bool fin = (cnt <= 256);
        // emit below-pivot actives; collect pivot-bin if final
        #pragma unroll
        for (int s = 0; s < 16; s++) {
            bool act = (level == 0) ? true
                     : (level == 1) ? ((k[s] >> 21) == pfx)
                                    : ((k[s] >> 10) == pfx);
            if (act) {
                int bin = (int)((k[s] >> shift) & bmask);
                if (bin < B) {
                    out[atomicAdd(&ctl[0], 1)] = t + (s << 8);
                } else if (bin == B && fin) {
                    cand[atomicAdd(&ctl[1], 1)] =
                        ((unsigned long long)k[s] << 32) | (unsigned)(t + (s << 8));
                }
            }
        }
        need = nneed;
        __syncthreads();
        if (fin) {
            int m = ctl[1];
            if (t >= m) cand[t] = ULLMAX;
            __syncthreads();
            #pragma unroll
            for (int k2 = 2; k2 <= 256; k2 <<= 1) {
                for (int j = k2 >> 1; j > 0; j >>= 1) {
                    int p = t ^ j;
                    if (p > t) {
                        unsigned long long a = cand[t], bb = cand[p];
                        bool up = ((t & k2) == 0);
                        if ((a > bb) == up) { cand[t] = bb; cand[p] = a; }
                    }
                    __syncthreads();
                }
            }
            if (t < need) out[ctl[0] + t] = (int)(cand[t] & 0xffffffffu);
            return;
        }
        pfx = (pfx << ((level == 2) ? 10 : 11)) | (unsigned)B;
    }
    // tie-break: >256 keys identical (== pfx); take smallest indices
    int oc = ctl[0];
    unsigned mymask = 0;
    #pragma unroll
    for (int s = 0; s < 16; s++)
        if (k[s] == pfx) mymask |= (1u << s);
    for (int r = 0; r < need; r++) {
        if (t == 0) ctl[5] = 0x7fffffff;
        __syncthreads();
        int myj = 0x7fffffff;
        if (mymask) myj = t + ((__ffs(mymask) - 1) << 8);
        if (myj != 0x7fffffff) atomicMin(&ctl[5], myj);
        __syncthreads();
        int win = ctl[5];
        if (myj == win) { mymask &= mymask - 1; out[oc + r] = win; }
        __syncthreads();
    }
}

// layer0: fused D=3 distance + selection (register keys, float4 loads)
__global__ __launch_bounds__(256) void knn0_k() {
    __shared__ unsigned hist[2048];
    __shared__ unsigned long long cand[256];
    __shared__ int wsum[8];
    __shared__ int ctl[8];
    int row = blockIdx.x;
    int base = row & ~(NN - 1);
    int t = threadIdx.x;
    float4 me = g_x4[row];
    unsigned k[16];
    #pragma unroll 4
    for (int s = 0; s < 16; s++) {
        float4 p = g_x4[base + t + (s << 8)];
        float dot = me.x * p.x + me.y * p.y + me.z * p.z;
        k[s] = okey(me.w + p.w - 2.f * dot);
    }
    select_reg(k, hist, cand, wsum, ctl, row);
}

// layer1: selection over precomputed distance keys
__global__ __launch_bounds__(256) void knn1_k() {
    __shared__ unsigned hist[2048];
    __shared__ unsigned long long cand[256];
    __shared__ int wsum[8];
    __shared__ int ctl[8];
    int row = blockIdx.x;
    int t = threadIdx.x;
    const unsigned* dr = g_distk + (size_t)row * NN;
    unsigned k[16];
    #pragma unroll 4
    for (int s = 0; s < 16; s++) k[s] = dr[t + (s << 8)];
    select_reg(k, hist, cand, wsum, ctl, row);
}

// ---------------- fused gather: BN stats + per-point neighbor vmax/vmin ------
template <int C>
__global__ __launch_bounds__(256) void gather_k() {
    constexpr int G = 256 / C;
    int t = threadIdx.x;
    int c = t % C;
    int g = t / C;
    float s = 0.f, s2 = 0.f;
    for (int p = blockIdx.x * G + g; p < NPTS; p += STATS_BLOCKS * G) {
        int b = p >> 12;
        float uc = g_u[(size_t)p * C + c];
        const int* ip = g_idx + p * KK;
        float S = 0.f, Q = 0.f, mx = -FINF, mn = FINF;
        #pragma unroll
        for (int k = 0; k < KK; k++) {
            int j = ip[k];
            float v = g_v[((size_t)((b << 12) + j)) * C + c];
            S += v;
            Q = fmaf(v, v, Q);
            mx = fmaxf(mx, v);
            mn = fminf(mn, v);
        }
        g_vmax[(size_t)p * C + c] = mx;
        g_vmin[(size_t)p * C + c] = mn;
        s += fmaf(20.f, uc, S);
        s2 += fmaf(20.f * uc, uc, fmaf(2.f * uc, S, Q));
    }
    __shared__ float sh[256], sh2[256];
    sh[t] = s; sh2[t] = s2;
    __syncthreads();
    if (t < C) {
        float S = sh[t], S2 = sh2[t];
        #pragma unroll
        for (int gg = 1; gg < G; gg++) { S += sh[gg * C + t]; S2 += sh2[gg * C + t]; }
        g_part[blockIdx.x * (2 * C) + t] = S;
        g_part[blockIdx.x * (2 * C) + C + t] = S2;
    }
}

template <int C>
__global__ void fin_k(const float* __restrict__ gamma, const float* __restrict__ beta) {
    int c = threadIdx.x;
    float S = 0.f, S2 = 0.f;
    for (int bk = 0; bk < STATS_BLOCKS; bk++) {
        S += g_part[bk * 2 * C + c];
        S2 += g_part[bk * 2 * C + C + c];
    }
    const float inv = 1.f / (float)EDG;
    float mu = S * inv;
    float var = S2 * inv - mu * mu;
    float sc = gamma[c] * rsqrtf(var + 1e-5f);
    g_scale[c] = sc;
    g_shift[c] = beta[c] - mu * sc;
}

// ---------------- finish: h = leaky(scale*(u + vmax/vmin) + shift) -----------
template <int C>
__global__ void finish_k() {
    int gid = blockIdx.x * 256 + threadIdx.x;    // NPTS*C
    int c = gid & (C - 1);
    float sc = g_scale[c];
    float vm = (sc >= 0.f) ? g_vmax[gid] : g_vmin[gid];
    float M = g_u[gid] + vm;
    float* out = (C == 64) ? (float*)g_h0 : (float*)g_h1;
    out[gid] = leaky(fmaf(M, sc, g_shift[c]));
}

// ---------------- attention gate + softmax -----------------------------------
__global__ void gate_k(const float* __restrict__ Wg, const float* __restrict__ bg) {
    int gt = blockIdx.x * 256 + threadIdx.x;
    int r = gt >> 5, lane = gt & 31;
    if (r >= NPTS) return;
    const float* h = g_h1 + (size_t)r * 256;
    float s = 0.f;
    #pragma unroll
    for (int q = 0; q < 8; q++) {
        int d = lane + (q << 5);
        s = fmaf(h[d], Wg[d], s);
    }
    #pragma unroll
    for (int o = 16; o; o >>= 1) s += __shfl_down_sync(0xffffffffu, s, o);
    if (lane == 0) {
        float gg = s + bg[0];
        g_gate[r] = gg > 0.f ? gg : 0.f;
    }
}

__global__ void softmax_k() {
    int b = blockIdx.x, t = threadIdx.x;
    __shared__ float sh[256];
    const float* gp = g_gate + (b << 12);
    float* ap = g_alpha + (b << 12);
    float mx = -FINF;
    for (int s = 0; s < 16; s++) mx = fmaxf(mx, gp[t + (s << 8)]);
    sh[t] = mx; __syncthreads();
    for (int o = 128; o; o >>= 1) { if (t < o) sh[t] = fmaxf(sh[t], sh[t + o]); __syncthreads(); }
    float M = sh[0];
    __syncthreads();
    float sum = 0.f;
    for (int s = 0; s < 16; s++) {
        int j = t + (s << 8);
        float e = expf(gp[j] - M);
        ap[j] = e;
        sum += e;
    }
    sh[t] = sum; __syncthreads();
    for (int o = 128; o; o >>= 1) { if (t < o) sh[t] += sh[t + o]; __syncthreads(); }
    float inv = 1.f / sh[0];
    for (int s = 0; s < 16; s++) ap[t + (s << 8)] *= inv;
}

// ---------------- fused feat GEMM + weighted pooling --------------------------
__global__ __launch_bounds__(256) void pool_k(const float* __restrict__ Wf,
                                              const float* __restrict__ bf) {
    int b = blockIdx.x;
    int t = threadIdx.x;
    int ch = blockIdx.y * 256 + t;
    int slab = blockIdx.z;
    __shared__ float hr[16][256];
    __shared__ float al[16];
    float acc = 0.f;
    float bfc = bf[ch];
    for (int gidx = 0; gidx < 8; gidx++) {
        int nb = (slab << 7) + (gidx << 4);
        __syncthreads();
        #pragma unroll
        for (int s = 0; s < 16; s++)
            hr[s][t] = g_h1[((size_t)(b << 12) + nb + s) * 256 + t];
        if (t < 16) al[t] = g_alpha[(b << 12) + nb + t];
        __syncthreads();
        float sacc[16];
        #pragma unroll
        for (int r = 0; r < 16; r++) sacc[r] = bfc;
        #pragma unroll 4
        for (int d = 0; d < 256; d += 4) {
            float w0 = Wf[(d + 0) * 512 + ch];
            float w1 = Wf[(d + 1) * 512 + ch];
            float w2 = Wf[(d + 2) * 512 + ch];
            float w3 = Wf[(d + 3) * 512 + ch];
            #pragma unroll
            for (int r = 0; r < 16; r++) {
                float4 hv = *(const float4*)&hr[r][d];
                sacc[r] = fmaf(hv.x, w0, fmaf(hv.y, w1, fmaf(hv.z, w2, fmaf(hv.w, w3, sacc[r]))));
            }
        }
        #pragma unroll
        for (int r = 0; r < 16; r++) {
            float f = sacc[r] > 0.f ? sacc[r] : 0.f;
            acc = fmaf(al[r], f, acc);
        }
    }
    g_pool[((slab << 2) + b) * 512 + ch] = acc;
}

__global__ void poolred_k() {
    int gid = blockIdx.x * 256 + threadIdx.x;  // BB*512
    if (gid >= BB * 512) return;
    int b = gid >> 9, ch = gid & 511;
    float s = 0.f;
    for (int sl = 0; sl < 32; sl++) s += g_pool[((sl << 2) + b) * 512 + ch];
    g_pooled[gid] = s;
}

__global__ void final_k(const float* __restrict__ Wl, const float* __restrict__ bl,
                        float* __restrict__ out) {
    int b = blockIdx.x, o = threadIdx.x;
    const float* p = g_pooled + b * 512;
    float s = bl[o];
    #pragma unroll 8
    for (int f = 0; f < 512; f++) s = fmaf(p[f], Wl[f * 256 + o], s);
    out[b * 256 + o] = s;
}

// ---------------- launch ------------------------------------------------------
extern "C" void kernel_launch(void* const* d_in, const int* in_sizes, int n_in,
                              void* d_out, int out_size) {
    (void)in_sizes; (void)n_in; (void)out_size;
    const float* x   = (const float*)d_in[0];
    const float* Wt0 = (const float*)d_in[1];
    const float* Wp0 = (const float*)d_in[3];
    const float* g0  = (const float*)d_in[5];
    const float* be0 = (const float*)d_in[6];
    const float* Wt1 = (const float*)d_in[7];
    const float* Wp1 = (const float*)d_in[9];
    const float* g1  = (const float*)d_in[11];
    const float* be1 = (const float*)d_in[12];
    const float* Wg  = (const float*)d_in[13];
    const float* bg  = (const float*)d_in[14];
    const float* Wf  = (const float*)d_in[15];
    const float* bf  = (const float*)d_in[16];
    const float* Wl  = (const float*)d_in[17];
    const float* bl  = (const float*)d_in[18];
    float* out = (float*)d_out;

    // ---- layer 0 ----
    prep_k<<<65, 256>>>(Wt0, Wp0, Wt1, Wp1);
    pack3_k<<<64, 256>>>(x);
    uv0_k<<<NPTS * 64 / 256, 256>>>(x, Wt0);
    knn0_k<<<NPTS, 256>>>();
    gather_k<64><<<STATS_BLOCKS, 256>>>();
    fin_k<64><<<1, 64>>>(g0, be0);
    finish_k<64><<<NPTS * 64 / 256, 256>>>();

    // ---- layer 1 ----
    norms64_k<<<NPTS * 32 / 256, 256>>>();
    gemm16_k<<<NPTS / 16, 256>>>(Wt1);
    dist_gemm_k<<<dim3(2080, BB), 256>>>();
    knn1_k<<<NPTS, 256>>>();
    gather_k<256><<<STATS_BLOCKS, 256>>>();
    fin_k<256><<<1, 256>>>(g1, be1);
    finish_k<256><<<NPTS * 256 / 256, 256>>>();

    // ---- attention pooling + final linear ----
    gate_k<<<NPTS * 32 / 256, 256>>>(Wg, bg);
    softmax_k<<<BB, 256>>>();
    pool_k<<<dim3(BB, 2, 32), 256>>>(Wf, bf);
    poolred_k<<<8, 256>>>();
    final_k<<<BB, 256>>>(Wl, bl, out);
}

// round 6
// speedup vs baseline: 1.0164x; 1.0164x over previous
#include <cuda_runtime.h>
#include <math.h>

#define BB 4
#define NN 4096
#define KK 20
#define NPTS (BB*NN)            // 16384
#define EDG  (NPTS*KK)          // 327680
#define STATS_BLOCKS 512

#define FINF __int_as_float(0x7f800000)
#define ULLMAX 0xFFFFFFFFFFFFFFFFULL

// ---------------- scratch (device globals; no allocations allowed) ----------
__device__ unsigned g_distk[(size_t)BB * NN * NN];  // order-keys of distances (layer 1)
__device__ float4 g_x4[NPTS];                        // packed (x,y,z,|x|^2)
__device__ float g_d2[NPTS];
__device__ int   g_idx[NPTS * KK];
__device__ float g_u[NPTS * 256];
__device__ float g_v[NPTS * 256];
__device__ float g_vmax[NPTS * 256];
__device__ float g_vmin[NPTS * 256];
__device__ float g_h0[NPTS * 64];
__device__ float g_h1[NPTS * 256];
__device__ float g_Wd0[3 * 64];
__device__ float g_Wd1[64 * 256];
__device__ float g_part[STATS_BLOCKS * 2 * 256];
__device__ float g_scale[256];
__device__ float g_shift[256];
__device__ float g_gate[NPTS];
__device__ float g_alpha[NPTS];
__device__ float g_pool[32 * BB * 512];
__device__ float g_pooled[BB * 512];

static __device__ __forceinline__ float leaky(float v) { return v > 0.f ? v : 0.2f * v; }

// float -> order-preserving uint (ascending float == ascending uint)
static __device__ __forceinline__ unsigned okey(float f) {
    unsigned u = __float_as_uint(f);
    return u ^ ((unsigned)(((int)u) >> 31) | 0x80000000u);
}

// ---------------- weight prep: Wd = Wp - Wt ---------------------------------
__global__ void prep_k(const float* __restrict__ Wt0, const float* __restrict__ Wp0,
                       const float* __restrict__ Wt1, const float* __restrict__ Wp1) {
    int i = blockIdx.x * 256 + threadIdx.x;
    if (i < 192) g_Wd0[i] = Wp0[i] - Wt0[i];
    int j = i - 192;
    if (j >= 0 && j < 16384) g_Wd1[j] = Wp1[j] - Wt1[j];
}

// ---------------- pack x + squared norm --------------------------------------
__global__ void pack3_k(const float* __restrict__ x) {
    int r = blockIdx.x * blockDim.x + threadIdx.x;
    if (r >= NPTS) return;
    float a = x[r * 3], b = x[r * 3 + 1], c = x[r * 3 + 2];
    g_x4[r] = make_float4(a, b, c, a * a + b * b + c * c);
}

__global__ void norms64_k() {
    int gt = blockIdx.x * blockDim.x + threadIdx.x;
    int r = gt >> 5, lane = gt & 31;
    if (r >= NPTS) return;
    const float* h = g_h0 + (size_t)r * 64;
    float a = h[lane], b = h[lane + 32];
    float s = a * a + b * b;
    #pragma unroll
    for (int o = 16; o; o >>= 1) s += __shfl_down_sync(0xffffffffu, s, o);
    if (lane == 0) g_d2[r] = s;
}

// ---------------- layer0 u/v (3->64, trivial) --------------------------------
__global__ void uv0_k(const float* __restrict__ x, const float* __restrict__ Wt0) {
    int gid = blockIdx.x * 256 + threadIdx.x;   // NPTS*64 total
    int r = gid >> 6, c = gid & 63;
    float x0 = x[r * 3], x1 = x[r * 3 + 1], x2 = x[r * 3 + 2];
    g_u[gid] = x0 * Wt0[c] + x1 * Wt0[64 + c] + x2 * Wt0[128 + c];
    g_v[gid] = x0 * g_Wd0[c] + x1 * g_Wd0[64 + c] + x2 * g_Wd0[128 + c];
}

// ---------------- fused 16-row (64->256) GEMM: u1 = h0@Wt1, v1 = h0@Wd1 ------
__global__ __launch_bounds__(256) void gemm16_k(const float* __restrict__ Wt1) {
    __shared__ float hs[16 * 64];
    int r0 = blockIdx.x * 16;
    int t = threadIdx.x;
    #pragma unroll
    for (int s = 0; s < 4; s++) {
        int l = t + (s << 8);
        hs[l] = g_h0[(size_t)r0 * 64 + l];
    }
    __syncthreads();
    float au[16], av[16];
    #pragma unroll
    for (int r = 0; r < 16; r++) { au[r] = 0.f; av[r] = 0.f; }
    #pragma unroll 4
    for (int d = 0; d < 64; d++) {
        float wu = Wt1[d * 256 + t];
        float wv = g_Wd1[d * 256 + t];
        #pragma unroll
        for (int r = 0; r < 16; r++) {
            float h = hs[r * 64 + d];
            au[r] = fmaf(h, wu, au[r]);
            av[r] = fmaf(h, wv, av[r]);
        }
    }
    #pragma unroll
    for (int r = 0; r < 16; r++) {
        g_u[(size_t)(r0 + r) * 256 + t] = au[r];
        g_v[(size_t)(r0 + r) * 256 + t] = av[r];
    }
}

// ---------------- distance GEMM (layer1), triangular grid, key output --------
static __device__ __forceinline__ int tri_start(int ti) {
    return ti * 64 - (ti * (ti - 1)) / 2;
}

__global__ __launch_bounds__(256) void dist_gemm_k() {
    const int b = blockIdx.y;
    int l = blockIdx.x;                    // 0..2079
    int ti = (int)((129.0f - sqrtf(129.0f * 129.0f - 8.0f * (float)l)) * 0.5f);
    if (ti > 63) ti = 63;
    while (ti < 63 && tri_start(ti + 1) <= l) ti++;
    while (ti > 0 && tri_start(ti) > l) ti--;
    int tj = ti + (l - tri_start(ti));
    const int i0 = ti * 64, j0 = tj * 64;
    __shared__ float As[64][65];
    __shared__ float Bs[64][65];
    const float* hb = g_h0 + (size_t)b * NN * 64;
    int t = threadIdx.x;
    #pragma unroll
    for (int s = 0; s < 16; s++) {
        int ll = t + (s << 8);
        int r = ll >> 6, d = ll & 63;
        As[d][r] = hb[(size_t)(i0 + r) * 64 + d];
        Bs[d][r] = hb[(size_t)(j0 + r) * 64 + d];
    }
    __syncthreads();
    int tx = t & 15, ty = t >> 4;
    float acc[4][4];
    #pragma unroll
    for (int r = 0; r < 4; r++)
        #pragma unroll
        for (int c = 0; c < 4; c++) acc[r][c] = 0.f;
    #pragma unroll 8
    for (int d = 0; d < 64; d++) {
        float a0 = As[d][ty * 4 + 0], a1 = As[d][ty * 4 + 1];
        float a2 = As[d][ty * 4 + 2], a3 = As[d][ty * 4 + 3];
        float b0 = Bs[d][tx * 4 + 0], b1 = Bs[d][tx * 4 + 1];
        float b2 = Bs[d][tx * 4 + 2], b3 = Bs[d][tx * 4 + 3];
        acc[0][0] = fmaf(a0, b0, acc[0][0]); acc[0][1] = fmaf(a0, b1, acc[0][1]);
        acc[0][2] = fmaf(a0, b2, acc[0][2]); acc[0][3] = fmaf(a0, b3, acc[0][3]);
        acc[1][0] = fmaf(a1, b0, acc[1][0]); acc[1][1] = fmaf(a1, b1, acc[1][1]);
        acc[1][2] = fmaf(a1, b2, acc[1][2]); acc[1][3] = fmaf(a1, b3, acc[1][3]);
        acc[2][0] = fmaf(a2, b0, acc[2][0]); acc[2][1] = fmaf(a2, b1, acc[2][1]);
        acc[2][2] = fmaf(a2, b2, acc[2][2]); acc[2][3] = fmaf(a2, b3, acc[2][3]);
        acc[3][0] = fmaf(a3, b0, acc[3][0]); acc[3][1] = fmaf(a3, b1, acc[3][1]);
        acc[3][2] = fmaf(a3, b2, acc[3][2]); acc[3][3] = fmaf(a3, b3, acc[3][3]);
    }
    const float* n2 = g_d2 + b * NN;
    float nj0 = n2[j0 + tx * 4 + 0], nj1 = n2[j0 + tx * 4 + 1];
    float nj2 = n2[j0 + tx * 4 + 2], nj3 = n2[j0 + tx * 4 + 3];
    unsigned kv[4][4];
    #pragma unroll
    for (int r = 0; r < 4; r++) {
        float ni = n2[i0 + ty * 4 + r];
        kv[r][0] = okey(ni + nj0 - 2.f * acc[r][0]);
        kv[r][1] = okey(ni + nj1 - 2.f * acc[r][1]);
        kv[r][2] = okey(ni + nj2 - 2.f * acc[r][2]);
        kv[r][3] = okey(ni + nj3 - 2.f * acc[r][3]);
        *(uint4*)&g_distk[((size_t)(b * NN + i0 + ty * 4 + r)) * NN + j0 + tx * 4] =
            make_uint4(kv[r][0], kv[r][1], kv[r][2], kv[r][3]);
    }
    if (ti != tj) {
        __syncthreads();
        unsigned* Ts = (unsigned*)&As[0][0];   // reuse [64][65]
        #pragma unroll
        for (int r = 0; r < 4; r++)
            #pragma unroll
            for (int c = 0; c < 4; c++)
                Ts[(tx * 4 + c) * 65 + (ty * 4 + r)] = kv[r][c];
        __syncthreads();
        #pragma unroll
        for (int s = 0; s < 16; s++) {
            int ll = t + (s << 8);
            int jr = ll >> 6, ic = ll & 63;
            g_distk[((size_t)(b * NN + j0 + jr)) * NN + i0 + ic] = Ts[jr * 65 + ic];
        }
    }
}

// ---------------- adaptive-range radix top-KK (keys in registers) -----------
// MODE 0: slot s of thread t -> element index t + s*256 (knn0)
// MODE 1: slot s -> uint4 component: idx = (t + (s>>2)*256)*4 + (s&3) (knn1)
template <int MODE>
static __device__ __forceinline__ int slot_idx(int t, int s) {
    return (MODE == 0) ? (t + (s << 8))
                       : (((t + ((s >> 2) << 8)) << 2) | (s & 3));
}

template <int MODE>
__device__ __forceinline__ void select_adapt(unsigned (&k)[16], unsigned* hist,
                                             unsigned long long* cand,
                                             int* wsum, int* ctl, int row) {
    const int t = threadIdx.x;
    const int lane = t & 31, w = t >> 5;
    int* out = g_idx + row * KK;

    // ---- block min/max of keys ----
    unsigned mn = 0xffffffffu, mx = 0u;
    #pragma unroll
    for (int s = 0; s < 16; s++) { mn = min(mn, k[s]); mx = max(mx, k[s]); }
    #pragma unroll
    for (int o = 16; o; o >>= 1) {
        mn = min(mn, __shfl_down_sync(0xffffffffu, mn, o));
        mx = max(mx, __shfl_down_sync(0xffffffffu, mx, o));
    }
    if (lane == 0) { hist[w] = mn; hist[8 + w] = mx; }   // borrow hist as scratch
    __syncthreads();
    if (t == 0) {
        unsigned m0 = hist[0], m1 = hist[8];
        #pragma unroll
        for (int i = 1; i < 8; i++) { m0 = min(m0, hist[i]); m1 = max(m1, hist[8 + i]); }
        ctl[5] = (int)m0; ctl[6] = (int)m1;
        ctl[0] = 0;
    }
    __syncthreads();
    unsigned lo = (unsigned)ctl[5];
    unsigned spread = (unsigned)ctl[6] - lo;
    int bits = (spread == 0u) ? 0 : (32 - __clz(spread));
    int sh = bits > 10 ? bits - 10 : 0;

    int need = KK;
    int rbits = 33;                 // level-0: everything active

    for (int lvl = 0; lvl < 5; lvl++) {
        // clear hist + init counters; pre-fill cand pad
        #pragma unroll
        for (int i = 0; i < 4; i++) hist[t * 4 + i] = 0;
        cand[t] = ULLMAX;
        if (t == 0) ctl[1] = 0;
        __syncthreads();
        // histogram active keys
        #pragma unroll
        for (int s = 0; s < 16; s++) {
            unsigned d = k[s] - lo;
            bool act = (rbits > 32) ? true : (d < (1u << rbits));
            unsigned bal = __ballot_sync(0xffffffffu, act);
            if (act) {
                unsigned bin = d >> sh;
                unsigned mm = __match_any_sync(bal, bin);
                if ((__ffs(mm) - 1) == lane) atomicAdd(&hist[bin], __popc(mm));
            }
        }
        __syncthreads();
        // inclusive scan over 1024 bins
        int lsum[4];
        int run = 0;
        #pragma unroll
        for (int i = 0; i < 4; i++) { run += (int)hist[t * 4 + i]; lsum[i] = run; }
        int inc = run;
        #pragma unroll
        for (int o = 1; o < 32; o <<= 1) {
            int n = __shfl_up_sync(0xffffffffu, inc, o);
            if (lane >= o) inc += n;
        }
        if (lane == 31) wsum[w] = inc;
        __syncthreads();
        if (t < 8) {
            int sv = wsum[t];
            #pragma unroll
            for (int o = 1; o < 8; o <<= 1) {
                int n = __shfl_up_sync(0xffu, sv, o);
                if (t >= o) sv += n;
            }
            wsum[t] = sv;
        }
        __syncthreads();
        int offs = (w ? wsum[w - 1] : 0) + (inc - run);
        #pragma unroll
        for (int i = 0; i < 4; i++) hist[t * 4 + i] = (unsigned)(lsum[i] + offs);
        __syncthreads();
        // pivot bin
        #pragma unroll
        for (int i = 0; i < 4; i++) {
            int bin = t * 4 + i;
            int cum = (int)hist[bin];
            int prev = bin ? (int)hist[bin - 1] : 0;
            if (cum >= need && prev < need) {
                ctl[2] = bin; ctl[3] = need - prev; ctl[4] = cum - prev;
            }
        }
        __syncthreads();
        const int B = ctl[2], nneed = ctl[3], cnt = ctl[4];
        const bool fin = (cnt <= 256);
        // emit below-pivot; collect pivot if final
        #pragma unroll
        for (int s = 0; s < 16; s++) {
            unsigned d = k[s] - lo;
            bool act = (rbits > 32) ? true : (d < (1u << rbits));
            if (act) {
                int bin = (int)(d >> sh);
                if (bin < B) {
                    out[atomicAdd(&ctl[0], 1)] = slot_idx<MODE>(t, s);
                } else if (bin == B && fin) {
                    cand[atomicAdd(&ctl[1], 1)] =
                        ((unsigned long long)k[s] << 32) | (unsigned)slot_idx<MODE>(t, s);
                }
            }
        }
        need = nneed;
        __syncthreads();
        if (fin) {
            // bitonic sort 256 u64 (key,idx) ascending; take `need`
            #pragma unroll
            for (int k2 = 2; k2 <= 256; k2 <<= 1) {
                for (int j = k2 >> 1; j > 0; j >>= 1) {
                    int p = t ^ j;
                    if (p > t) {
                        unsigned long long a = cand[t], bb = cand[p];
                        bool up = ((t & k2) == 0);
                        if ((a > bb) == up) { cand[t] = bb; cand[p] = a; }
                    }
                    __syncthreads();
                }
            }
            if (t < need) out[ctl[0] + t] = (int)(cand[t] & 0xffffffffu);
            return;
        }
        if (sh == 0) {
            // pivot bin = one exact key value, >256 duplicates: smallest indices win
            unsigned mymask = 0;
            #pragma unroll
            for (int s = 0; s < 16; s++)
                if (k[s] - lo == (unsigned)B) mymask |= (1u << s);
            int oc = ctl[0];
            for (int r = 0; r < need; r++) {
                if (t == 0) ctl[7] = 0x7fffffff;
                __syncthreads();
                if (mymask) {
                    int myj = slot_idx<MODE>(t, __ffs(mymask) - 1);
                    atomicMin(&ctl[7], myj);
                }
                __syncthreads();
                int win = ctl[7];
                if (mymask) {
                    int sbit = __ffs(mymask) - 1;
                    if (slot_idx<MODE>(t, sbit) == win) {
                        mymask &= mymask - 1;
                        out[oc + r] = win;
                    }
                }
                __syncthreads();
            }
            return;
        }
        lo += ((unsigned)B) << sh;
        rbits = sh;
        sh = (sh > 10) ? sh - 10 : 0;
    }
}

// layer0: fused D=3 distance + selection
__global__ __launch_bounds__(256, 5) void knn0_k() {
    __shared__ unsigned hist[1024];
    __shared__ unsigned long long cand[256];
    __shared__ int wsum[8];
    __shared__ int ctl[8];
    int row = blockIdx.x;
    int base = row & ~(NN - 1);
    int t = threadIdx.x;
    float4 me = g_x4[row];
    unsigned k[16];
    #pragma unroll 4
    for (int s = 0; s < 16; s++) {
        float4 p = g_x4[base + t + (s << 8)];
        float dot = me.x * p.x + me.y * p.y + me.z * p.z;
        k[s] = okey(me.w + p.w - 2.f * dot);
    }
    select_adapt<0>(k, hist, cand, wsum, ctl, row);
}

// layer1: selection over precomputed distance keys (vectorized loads)
__global__ __launch_bounds__(256, 5) void knn1_k() {
    __shared__ unsigned hist[1024];
    __shared__ unsigned long long cand[256];
    __shared__ int wsum[8];
    __shared__ int ctl[8];
    int row = blockIdx.x;
    int t = threadIdx.x;
    const uint4* dr = (const uint4*)(g_distk + (size_t)row * NN);
    unsigned k[16];
    #pragma unroll
    for (int s = 0; s < 4; s++) {
        uint4 d4 = dr[t + (s << 8)];
        k[s * 4 + 0] = d4.x;
        k[s * 4 + 1] = d4.y;
        k[s * 4 + 2] = d4.z;
        k[s * 4 + 3] = d4.w;
    }
    select_adapt<1>(k, hist, cand, wsum, ctl, row);
}

// ---------------- fused gather: BN stats + per-point neighbor vmax/vmin ------
template <int C>
__global__ __launch_bounds__(256) void gather_k() {
    constexpr int G = 256 / C;
    int t = threadIdx.x;
    int c = t % C;
    int g = t / C;
    float s = 0.f, s2 = 0.f;
    for (int p = blockIdx.x * G + g; p < NPTS; p += STATS_BLOCKS * G) {
        int b = p >> 12;
        float uc = g_u[(size_t)p * C + c];
        const int* ip = g_idx + p * KK;
        float S = 0.f, Q = 0.f, mx = -FINF, mn = FINF;
        #pragma unroll
        for (int k = 0; k < KK; k++) {
            int j = ip[k];
            float v = g_v[((size_t)((b << 12) + j)) * C + c];
            S += v;
            Q = fmaf(v, v, Q);
            mx = fmaxf(mx, v);
            mn = fminf(mn, v);
        }
        g_vmax[(size_t)p * C + c] = mx;
        g_vmin[(size_t)p * C + c] = mn;
        s += fmaf(20.f, uc, S);
        s2 += fmaf(20.f * uc, uc, fmaf(2.f * uc, S, Q));
    }
    __shared__ float sh[256], sh2[256];
    sh[t] = s; sh2[t] = s2;
    __syncthreads();
    if (t < C) {
        float S = sh[t], S2 = sh2[t];
        #pragma unroll
        for (int gg = 1; gg < G; gg++) { S += sh[gg * C + t]; S2 += sh2[gg * C + t]; }
        g_part[blockIdx.x * (2 * C) + t] = S;
        g_part[blockIdx.x * (2 * C) + C + t] = S2;
    }
}

template <int C>
__global__ void fin_k(const float* __restrict__ gamma, const float* __restrict__ beta) {
    int c = threadIdx.x;
    float S = 0.f, S2 = 0.f;
    for (int bk = 0; bk < STATS_BLOCKS; bk++) {
        S += g_part[bk * 2 * C + c];
        S2 += g_part[bk * 2 * C + C + c];
    }
    const float inv = 1.f / (float)EDG;
    float mu = S * inv;
    float var = S2 * inv - mu * mu;
    float sc = gamma[c] * rsqrtf(var + 1e-5f);
    g_scale[c] = sc;
    g_shift[c] = beta[c] - mu * sc;
}

// ---------------- finish: h = leaky(scale*(u + vmax/vmin) + shift) -----------
template <int C>
__global__ void finish_k() {
    int gid = blockIdx.x * 256 + threadIdx.x;    // NPTS*C
    int c = gid & (C - 1);
    float sc = g_scale[c];
    float vm = (sc >= 0.f) ? g_vmax[gid] : g_vmin[gid];
    float M = g_u[gid] + vm;
    float* out = (C == 64) ? (float*)g_h0 : (float*)g_h1;
    out[gid] = leaky(fmaf(M, sc, g_shift[c]));
}

// ---------------- attention gate + softmax -----------------------------------
__global__ void gate_k(const float* __restrict__ Wg, const float* __restrict__ bg) {
    int gt = blockIdx.x * 256 + threadIdx.x;
    int r = gt >> 5, lane = gt & 31;
    if (r >= NPTS) return;
    const float* h = g_h1 + (size_t)r * 256;
    float s = 0.f;
    #pragma unroll
    for (int q = 0; q < 8; q++) {
        int d = lane + (q << 5);
        s = fmaf(h[d], Wg[d], s);
    }
    #pragma unroll
    for (int o = 16; o; o >>= 1) s += __shfl_down_sync(0xffffffffu, s, o);
    if (lane == 0) {
        float gg = s + bg[0];
        g_gate[r] = gg > 0.f ? gg : 0.f;
    }
}

__global__ void softmax_k() {
    int b = blockIdx.x, t = threadIdx.x;
    __shared__ float sh[256];
    const float* gp = g_gate + (b << 12);
    float* ap = g_alpha + (b << 12);
    float mx = -FINF;
    for (int s = 0; s < 16; s++) mx = fmaxf(mx, gp[t + (s << 8)]);
    sh[t] = mx; __syncthreads();
    for (int o = 128; o; o >>= 1) { if (t < o) sh[t] = fmaxf(sh[t], sh[t + o]); __syncthreads(); }
    float M = sh[0];
    __syncthreads();
    float sum = 0.f;
    for (int s = 0; s < 16; s++) {
        int j = t + (s << 8);
        float e = expf(gp[j] - M);
        ap[j] = e;
        sum += e;
    }
    sh[t] = sum; __syncthreads();
    for (int o = 128; o; o >>= 1) { if (t < o) sh[t] += sh[t + o]; __syncthreads(); }
    float inv = 1.f / sh[0];
    for (int s = 0; s < 16; s++) ap[t + (s << 8)] *= inv;
}

// ---------------- fused feat GEMM + weighted pooling --------------------------
__global__ __launch_bounds__(256) void pool_k(const float* __restrict__ Wf,
                                              const float* __restrict__ bf) {
    int b = blockIdx.x;
    int t = threadIdx.x;
    int ch = blockIdx.y * 256 + t;
    int slab = blockIdx.z;
    __shared__ float hr[16][256];
    __shared__ float al[16];
    float acc = 0.f;
    float bfc = bf[ch];
    for (int gidx = 0; gidx < 8; gidx++) {
        int nb = (slab << 7) + (gidx << 4);
        __syncthreads();
        #pragma unroll
        for (int s = 0; s < 16; s++)
            hr[s][t] = g_h1[((size_t)(b << 12) + nb + s) * 256 + t];
        if (t < 16) al[t] = g_alpha[(b << 12) + nb + t];
        __syncthreads();
        float sacc[16];
        #pragma unroll
        for (int r = 0; r < 16; r++) sacc[r] = bfc;
        #pragma unroll 4
        for (int d = 0; d < 256; d += 4) {
            float w0 = Wf[(d + 0) * 512 + ch];
            float w1 = Wf[(d + 1) * 512 + ch];
            float w2 = Wf[(d + 2) * 512 + ch];
            float w3 = Wf[(d + 3) * 512 + ch];
            #pragma unroll
            for (int r = 0; r < 16; r++) {
                float4 hv = *(const float4*)&hr[r][d];
                sacc[r] = fmaf(hv.x, w0, fmaf(hv.y, w1, fmaf(hv.z, w2, fmaf(hv.w, w3, sacc[r]))));
            }
        }
        #pragma unroll
        for (int r = 0; r < 16; r++) {
            float f = sacc[r] > 0.f ? sacc[r] : 0.f;
            acc = fmaf(al[r], f, acc);
        }
    }
    g_pool[((slab << 2) + b) * 512 + ch] = acc;
}

__global__ void poolred_k() {
    int gid = blockIdx.x * 256 + threadIdx.x;  // BB*512
    if (gid >= BB * 512) return;
    int b = gid >> 9, ch = gid & 511;
    float s = 0.f;
    for (int sl = 0; sl < 32; sl++) s += g_pool[((sl << 2) + b) * 512 + ch];
    g_pooled[gid] = s;
}

__global__ void final_k(const float* __restrict__ Wl, const float* __restrict__ bl,
                        float* __restrict__ out) {
    int b = blockIdx.x, o = threadIdx.x;
    const float* p = g_pooled + b * 512;
    float s = bl[o];
    #pragma unroll 8
    for (int f = 0; f < 512; f++) s = fmaf(p[f], Wl[f * 256 + o], s);
    out[b * 256 + o] = s;
}

// ---------------- launch ------------------------------------------------------
extern "C" void kernel_launch(void* const* d_in, const int* in_sizes, int n_in,
                              void* d_out, int out_size) {
    (void)in_sizes; (void)n_in; (void)out_size;
    const float* x   = (const float*)d_in[0];
    const float* Wt0 = (const float*)d_in[1];
    const float* Wp0 = (const float*)d_in[3];
    const float* g0  = (const float*)d_in[5];
    const float* be0 = (const float*)d_in[6];
    const float* Wt1 = (const float*)d_in[7];
    const float* Wp1 = (const float*)d_in[9];
    const float* g1  = (const float*)d_in[11];
    const float* be1 = (const float*)d_in[12];
    const float* Wg  = (const float*)d_in[13];
    const float* bg  = (const float*)d_in[14];
    const float* Wf  = (const float*)d_in[15];
    const float* bf  = (const float*)d_in[16];
    const float* Wl  = (const float*)d_in[17];
    const float* bl  = (const float*)d_in[18];
    float* out = (float*)d_out;

    // ---- layer 0 ----
    prep_k<<<65, 256>>>(Wt0, Wp0, Wt1, Wp1);
    pack3_k<<<64, 256>>>(x);
    uv0_k<<<NPTS * 64 / 256, 256>>>(x, Wt0);
    knn0_k<<<NPTS, 256>>>();
    gather_k<64><<<STATS_BLOCKS, 256>>>();
    fin_k<64><<<1, 64>>>(g0, be0);
    finish_k<64><<<NPTS * 64 / 256, 256>>>();

    // ---- layer 1 ----
    norms64_k<<<NPTS * 32 / 256, 256>>>();
    gemm16_k<<<NPTS / 16, 256>>>(Wt1);
    dist_gemm_k<<<dim3(2080, BB), 256>>>();
    knn1_k<<<NPTS, 256>>>();
    gather_k<256><<<STATS_BLOCKS, 256>>>();
    fin_k<256><<<1, 256>>>(g1, be1);
    finish_k<256><<<NPTS * 256 / 256, 256>>>();

    // ---- attention pooling + final linear ----
    gate_k<<<NPTS * 32 / 256, 256>>>(Wg, bg);
    softmax_k<<<BB, 256>>>();
    pool_k<<<dim3(BB, 2, 32), 256>>>(Wf, bf);
    poolred_k<<<8, 256>>>();
    final_k<<<BB, 256>>>(Wl, bl, out);
}

// round 7
// speedup vs baseline: 1.1146x; 1.0966x over previous
#include <cuda_runtime.h>
#include <math.h>

#define BB 4
#define NN 4096
#define KK 20
#define NPTS (BB*NN)            // 16384
#define EDG  (NPTS*KK)          // 327680
#define STATS_BLOCKS 512

#define FINF __int_as_float(0x7f800000)
#define ULLMAX 0xFFFFFFFFFFFFFFFFULL

// ---------------- scratch (device globals; no allocations allowed) ----------
__device__ unsigned g_distk[(size_t)BB * NN * NN];  // order-keys of distances (layer 1)
__device__ float4 g_x4[NPTS];                        // packed (x,y,z,|x|^2)
__device__ float g_d2[NPTS];
__device__ int   g_idx[NPTS * KK];
__device__ float g_u[NPTS * 256];
__device__ float g_v[NPTS * 256];
__device__ float g_vmax[NPTS * 256];
__device__ float g_vmin[NPTS * 256];
__device__ float g_h0[NPTS * 64];
__device__ float g_h1[NPTS * 256];
__device__ float g_Wd0[3 * 64];
__device__ float g_Wd1[64 * 256];
__device__ float g_part[STATS_BLOCKS * 2 * 256];
__device__ float g_scale[256];
__device__ float g_shift[256];
__device__ float g_gate[NPTS];
__device__ float g_alpha[NPTS];
__device__ float g_pool[32 * BB * 512];
__device__ float g_pooled[BB * 512];

static __device__ __forceinline__ float leaky(float v) { return v > 0.f ? v : 0.2f * v; }

// float -> order-preserving uint (ascending float == ascending uint)
static __device__ __forceinline__ unsigned okey(float f) {
    unsigned u = __float_as_uint(f);
    return u ^ ((unsigned)(((int)u) >> 31) | 0x80000000u);
}

// ---------------- weight prep: Wd = Wp - Wt ---------------------------------
__global__ void prep_k(const float* __restrict__ Wt0, const float* __restrict__ Wp0,
                       const float* __restrict__ Wt1, const float* __restrict__ Wp1) {
    int i = blockIdx.x * 256 + threadIdx.x;
    if (i < 192) g_Wd0[i] = Wp0[i] - Wt0[i];
    int j = i - 192;
    if (j >= 0 && j < 16384) g_Wd1[j] = Wp1[j] - Wt1[j];
}

// ---------------- pack x + squared norm --------------------------------------
__global__ void pack3_k(const float* __restrict__ x) {
    int r = blockIdx.x * blockDim.x + threadIdx.x;
    if (r >= NPTS) return;
    float a = x[r * 3], b = x[r * 3 + 1], c = x[r * 3 + 2];
    g_x4[r] = make_float4(a, b, c, a * a + b * b + c * c);
}

__global__ void norms64_k() {
    int gt = blockIdx.x * blockDim.x + threadIdx.x;
    int r = gt >> 5, lane = gt & 31;
    if (r >= NPTS) return;
    const float* h = g_h0 + (size_t)r * 64;
    float a = h[lane], b = h[lane + 32];
    float s = a * a + b * b;
    #pragma unroll
    for (int o = 16; o; o >>= 1) s += __shfl_down_sync(0xffffffffu, s, o);
    if (lane == 0) g_d2[r] = s;
}

// ---------------- layer0 u/v (3->64, trivial) --------------------------------
__global__ void uv0_k(const float* __restrict__ x, const float* __restrict__ Wt0) {
    int gid = blockIdx.x * 256 + threadIdx.x;   // NPTS*64 total
    int r = gid >> 6, c = gid & 63;
    float x0 = x[r * 3], x1 = x[r * 3 + 1], x2 = x[r * 3 + 2];
    g_u[gid] = x0 * Wt0[c] + x1 * Wt0[64 + c] + x2 * Wt0[128 + c];
    g_v[gid] = x0 * g_Wd0[c] + x1 * g_Wd0[64 + c] + x2 * g_Wd0[128 + c];
}

// ---------------- fused 16-row (64->256) GEMM: u1 = h0@Wt1, v1 = h0@Wd1 ------
__global__ __launch_bounds__(256) void gemm16_k(const float* __restrict__ Wt1) {
    __shared__ float hs[16 * 64];
    int r0 = blockIdx.x * 16;
    int t = threadIdx.x;
    #pragma unroll
    for (int s = 0; s < 4; s++) {
        int l = t + (s << 8);
        hs[l] = g_h0[(size_t)r0 * 64 + l];
    }
    __syncthreads();
    float au[16], av[16];
    #pragma unroll
    for (int r = 0; r < 16; r++) { au[r] = 0.f; av[r] = 0.f; }
    #pragma unroll 4
    for (int d = 0; d < 64; d++) {
        float wu = Wt1[d * 256 + t];
        float wv = g_Wd1[d * 256 + t];
        #pragma unroll
        for (int r = 0; r < 16; r++) {
            float h = hs[r * 64 + d];
            au[r] = fmaf(h, wu, au[r]);
            av[r] = fmaf(h, wv, av[r]);
        }
    }
    #pragma unroll
    for (int r = 0; r < 16; r++) {
        g_u[(size_t)(r0 + r) * 256 + t] = au[r];
        g_v[(size_t)(r0 + r) * 256 + t] = av[r];
    }
}

// ---------------- distance GEMM (layer1), triangular grid, key output --------
static __device__ __forceinline__ int tri_start(int ti) {
    return ti * 64 - (ti * (ti - 1)) / 2;
}

__global__ __launch_bounds__(256) void dist_gemm_k() {
    const int b = blockIdx.y;
    int l = blockIdx.x;                    // 0..2079
    int ti = (int)((129.0f - sqrtf(129.0f * 129.0f - 8.0f * (float)l)) * 0.5f);
    if (ti > 63) ti = 63;
    while (ti < 63 && tri_start(ti + 1) <= l) ti++;
    while (ti > 0 && tri_start(ti) > l) ti--;
    int tj = ti + (l - tri_start(ti));
    const int i0 = ti * 64, j0 = tj * 64;
    __shared__ float As[64][65];
    __shared__ float Bs[64][65];
    const float* hb = g_h0 + (size_t)b * NN * 64;
    int t = threadIdx.x;
    #pragma unroll
    for (int s = 0; s < 16; s++) {
        int ll = t + (s << 8);
        int r = ll >> 6, d = ll & 63;
        As[d][r] = hb[(size_t)(i0 + r) * 64 + d];
        Bs[d][r] = hb[(size_t)(j0 + r) * 64 + d];
    }
    __syncthreads();
    int tx = t & 15, ty = t >> 4;
    float acc[4][4];
    #pragma unroll
    for (int r = 0; r < 4; r++)
        #pragma unroll
        for (int c = 0; c < 4; c++) acc[r][c] = 0.f;
    #pragma unroll 8
    for (int d = 0; d < 64; d++) {
        float a0 = As[d][ty * 4 + 0], a1 = As[d][ty * 4 + 1];
        float a2 = As[d][ty * 4 + 2], a3 = As[d][ty * 4 + 3];
        float b0 = Bs[d][tx * 4 + 0], b1 = Bs[d][tx * 4 + 1];
        float b2 = Bs[d][tx * 4 + 2], b3 = Bs[d][tx * 4 + 3];
        acc[0][0] = fmaf(a0, b0, acc[0][0]); acc[0][1] = fmaf(a0, b1, acc[0][1]);
        acc[0][2] = fmaf(a0, b2, acc[0][2]); acc[0][3] = fmaf(a0, b3, acc[0][3]);
        acc[1][0] = fmaf(a1, b0, acc[1][0]); acc[1][1] = fmaf(a1, b1, acc[1][1]);
        acc[1][2] = fmaf(a1, b2, acc[1][2]); acc[1][3] = fmaf(a1, b3, acc[1][3]);
        acc[2][0] = fmaf(a2, b0, acc[2][0]); acc[2][1] = fmaf(a2, b1, acc[2][1]);
        acc[2][2] = fmaf(a2, b2, acc[2][2]); acc[2][3] = fmaf(a2, b3, acc[2][3]);
        acc[3][0] = fmaf(a3, b0, acc[3][0]); acc[3][1] = fmaf(a3, b1, acc[3][1]);
        acc[3][2] = fmaf(a3, b2, acc[3][2]); acc[3][3] = fmaf(a3, b3, acc[3][3]);
    }
    const float* n2 = g_d2 + b * NN;
    float nj0 = n2[j0 + tx * 4 + 0], nj1 = n2[j0 + tx * 4 + 1];
    float nj2 = n2[j0 + tx * 4 + 2], nj3 = n2[j0 + tx * 4 + 3];
    unsigned kv[4][4];
    #pragma unroll
    for (int r = 0; r < 4; r++) {
        float ni = n2[i0 + ty * 4 + r];
        kv[r][0] = okey(ni + nj0 - 2.f * acc[r][0]);
        kv[r][1] = okey(ni + nj1 - 2.f * acc[r][1]);
        kv[r][2] = okey(ni + nj2 - 2.f * acc[r][2]);
        kv[r][3] = okey(ni + nj3 - 2.f * acc[r][3]);
        *(uint4*)&g_distk[((size_t)(b * NN + i0 + ty * 4 + r)) * NN + j0 + tx * 4] =
            make_uint4(kv[r][0], kv[r][1], kv[r][2], kv[r][3]);
    }
    if (ti != tj) {
        __syncthreads();
        unsigned* Ts = (unsigned*)&As[0][0];   // reuse [64][65]
        #pragma unroll
        for (int r = 0; r < 4; r++)
            #pragma unroll
            for (int c = 0; c < 4; c++)
                Ts[(tx * 4 + c) * 65 + (ty * 4 + r)] = kv[r][c];
        __syncthreads();
        #pragma unroll
        for (int s = 0; s < 16; s++) {
            int ll = t + (s << 8);
            int jr = ll >> 6, ic = ll & 63;
            g_distk[((size_t)(b * NN + j0 + jr)) * NN + i0 + ic] = Ts[jr * 65 + ic];
        }
    }
}

// ---------------- atomic-free radix top-KK (per-thread u8 histograms) --------
// MODE 0: slot s of thread t -> element index t + s*256 (knn0)
// MODE 1: slot s -> uint4 component: idx = (t + (s>>2)*256)*4 + (s&3) (knn1)
template <int MODE>
static __device__ __forceinline__ int slot_idx(int t, int s) {
    return (MODE == 0) ? (t + (s << 8))
                       : (((t + ((s >> 2) << 8)) << 2) | (s & 3));
}

// hist: 64 bins x 64 thread-groups u32 (each u32 = 4 thread byte-counters),
// XOR-swizzled: word(g,bin) = g*64 + (bin ^ g). 16 KB.
template <int MODE>
__device__ __forceinline__ void select64(unsigned (&k)[16], unsigned* hist,
                                         int* tot, unsigned long long* cand,
                                         int* ctl, int row) {
    const int t = threadIdx.x;
    const int lane = t & 31, w = t >> 5;
    const int g = t >> 2, q = t & 3;
    int* out = g_idx + row * KK;

    // ---- block min/max ----
    unsigned mn = 0xffffffffu, mx = 0u;
    #pragma unroll
    for (int s = 0; s < 16; s++) { mn = min(mn, k[s]); mx = max(mx, k[s]); }
    #pragma unroll
    for (int o = 16; o; o >>= 1) {
        mn = min(mn, __shfl_xor_sync(0xffffffffu, mn, o));
        mx = max(mx, __shfl_xor_sync(0xffffffffu, mx, o));
    }
    if (lane == 0) { tot[w] = (int)mn; tot[8 + w] = (int)mx; }
    __syncthreads();
    if (t == 0) {
        unsigned m0 = (unsigned)tot[0], m1 = (unsigned)tot[8];
        #pragma unroll
        for (int i = 1; i < 8; i++) {
            m0 = min(m0, (unsigned)tot[i]);
            m1 = max(m1, (unsigned)tot[8 + i]);
        }
        ctl[5] = (int)m0; ctl[6] = (int)m1; ctl[0] = 0;
    }
    __syncthreads();
    unsigned lo = (unsigned)ctl[5];
    unsigned spread = (unsigned)ctl[6] - lo;
    int bits = (spread == 0u) ? 0 : (32 - __clz(spread));
    int sh = bits > 6 ? bits - 6 : 0;
    int need = KK;
    bool all = true;
    unsigned rwidth = 0;

    for (int lvl = 0; lvl < 8; lvl++) {
        // clear private hist + counters
        #pragma unroll
        for (int i = 0; i < 16; i++) hist[t + (i << 8)] = 0u;
        if (t == 0) ctl[1] = 0;
        __syncthreads();
        // per-thread u8 histogram (no atomics; thread owns byte q of its g-column)
        unsigned char* h8 = (unsigned char*)hist;
        #pragma unroll
        for (int s = 0; s < 16; s++) {
            unsigned d = k[s] - lo;
            if (all || d < rwidth) {
                unsigned bin = d >> sh;                    // 0..63
                unsigned word = (unsigned)(g << 6) + (bin ^ (unsigned)g);
                unsigned addr = (word << 2) | (unsigned)q;
                h8[addr] = (unsigned char)(h8[addr] + 1);
            }
        }
        __syncthreads();
        // reduce: thread t sums bin=t>>2 over its quarter of the 64 groups
        {
            int bin = t >> 2;
            unsigned acc = 0;
            #pragma unroll
            for (int gg = 0; gg < 16; gg++) {
                int G = (q << 4) + gg;
                unsigned wv = hist[(G << 6) + (bin ^ G)];
                acc = __dp4a(wv, 0x01010101u, acc);
            }
            acc += __shfl_xor_sync(0xffffffffu, acc, 1);
            acc += __shfl_xor_sync(0xffffffffu, acc, 2);
            if (q == 0) tot[bin] = (int)acc;
        }
        __syncthreads();
        // inclusive scan of 64 bins on warp 0
        if (w == 0) {
            int a = tot[lane], b2 = tot[lane + 32];
            #pragma unroll
            for (int o = 1; o < 32; o <<= 1) {
                int n = __shfl_up_sync(0xffffffffu, a, o);
                if (lane >= o) a += n;
            }
            #pragma unroll
            for (int o = 1; o < 32; o <<= 1) {
                int n = __shfl_up_sync(0xffffffffu, b2, o);
                if (lane >= o) b2 += n;
            }
            b2 += __shfl_sync(0xffffffffu, a, 31);
            tot[lane] = a; tot[lane + 32] = b2;
        }
        __syncthreads();
        // pivot bin
        if (t < 64) {
            int cum = tot[t], prev = t ? tot[t - 1] : 0;
            if (cum >= need && prev < need) {
                ctl[2] = t; ctl[3] = need - prev; ctl[4] = cum - prev;
            }
        }
        __syncthreads();
        const int B = ctl[2], nneed = ctl[3], cnt = ctl[4];
        const bool fin = (cnt <= 64);
        // emit below-pivot; collect pivot-bin candidates if final
        #pragma unroll
        for (int s = 0; s < 16; s++) {
            unsigned d = k[s] - lo;
            if (all || d < rwidth) {
                int bin = (int)(d >> sh);
                if (bin < B) {
                    out[atomicAdd(&ctl[0], 1)] = slot_idx<MODE>(t, s);
                } else if (bin == B && fin) {
                    cand[atomicAdd(&ctl[1], 1)] =
                        ((unsigned long long)k[s] << 32) | (unsigned)slot_idx<MODE>(t, s);
                }
            }
        }
        need = nneed;
        __syncthreads();
        if (fin) {
            // warp-0 pop-sort of <=64 unique u64s; smallest `need` in order
            if (w == 0) {
                int m = ctl[1];
                unsigned long long a = (lane < m) ? cand[lane] : ULLMAX;
                unsigned long long b2 = (lane + 32 < m) ? cand[lane + 32] : ULLMAX;
                unsigned long long cl = min(a, b2), ch = max(a, b2);
                int oc = ctl[0];
                for (int r = 0; r < need; r++) {
                    unsigned long long v = cl;
                    #pragma unroll
                    for (int o = 16; o; o >>= 1) {
                        unsigned long long ov = __shfl_xor_sync(0xffffffffu, v, o);
                        v = min(v, ov);
                    }
                    if (cl == v) { out[oc + r] = (int)(v & 0xffffffffu); cl = ch; ch = ULLMAX; }
                }
            }
            return;
        }
        if (sh == 0) {
            // >64 duplicates of exact key (lo+B): smallest indices win
            unsigned mymask = 0;
            #pragma unroll
            for (int s = 0; s < 16; s++)
                if (k[s] - lo == (unsigned)B) mymask |= (1u << s);
            int oc = ctl[0];
            for (int r = 0; r < need; r++) {
                if (t == 0) ctl[7] = 0x7fffffff;
                __syncthreads();
                if (mymask) atomicMin(&ctl[7], slot_idx<MODE>(t, __ffs(mymask) - 1));
                __syncthreads();
                int win = ctl[7];
                if (mymask && slot_idx<MODE>(t, __ffs(mymask) - 1) == win) {
                    mymask &= mymask - 1;
                    out[oc + r] = win;
                }
                __syncthreads();
            }
            return;
        }
        lo += ((unsigned)B) << sh;
        all = false;
        rwidth = 1u << sh;
        sh = (sh > 6) ? sh - 6 : 0;
    }
}

// layer0: fused D=3 distance + selection
__global__ __launch_bounds__(256) void knn0_k() {
    __shared__ unsigned hist[4096];          // 16 KB
    __shared__ int tot[64];
    __shared__ unsigned long long cand[64];
    __shared__ int ctl[8];
    int row = blockIdx.x;
    int base = row & ~(NN - 1);
    int t = threadIdx.x;
    float4 me = g_x4[row];
    unsigned k[16];
    #pragma unroll 4
    for (int s = 0; s < 16; s++) {
        float4 p = g_x4[base + t + (s << 8)];
        float dot = me.x * p.x + me.y * p.y + me.z * p.z;
        k[s] = okey(me.w + p.w - 2.f * dot);
    }
    select64<0>(k, hist, tot, cand, ctl, row);
}

// layer1: selection over precomputed distance keys (vectorized loads)
__global__ __launch_bounds__(256) void knn1_k() {
    __shared__ unsigned hist[4096];
    __shared__ int tot[64];
    __shared__ unsigned long long cand[64];
    __shared__ int ctl[8];
    int row = blockIdx.x;
    int t = threadIdx.x;
    const uint4* dr = (const uint4*)(g_distk + (size_t)row * NN);
    unsigned k[16];
    #pragma unroll
    for (int s = 0; s < 4; s++) {
        uint4 d4 = dr[t + (s << 8)];
        k[s * 4 + 0] = d4.x;
        k[s * 4 + 1] = d4.y;
        k[s * 4 + 2] = d4.z;
        k[s * 4 + 3] = d4.w;
    }
    select64<1>(k, hist, tot, cand, ctl, row);
}

// ---------------- fused gather: BN stats + per-point neighbor vmax/vmin ------
template <int C>
__global__ __launch_bounds__(256) void gather_k() {
    constexpr int G = 256 / C;
    int t = threadIdx.x;
    int c = t % C;
    int g = t / C;
    float s = 0.f, s2 = 0.f;
    for (int p = blockIdx.x * G + g; p < NPTS; p += STATS_BLOCKS * G) {
        int b = p >> 12;
        float uc = g_u[(size_t)p * C + c];
        const int* ip = g_idx + p * KK;
        float S = 0.f, Q = 0.f, mx = -FINF, mn = FINF;
        #pragma unroll
        for (int k = 0; k < KK; k++) {
            int j = ip[k];
            float v = g_v[((size_t)((b << 12) + j)) * C + c];
            S += v;
            Q = fmaf(v, v, Q);
            mx = fmaxf(mx, v);
            mn = fminf(mn, v);
        }
        g_vmax[(size_t)p * C + c] = mx;
        g_vmin[(size_t)p * C + c] = mn;
        s += fmaf(20.f, uc, S);
        s2 += fmaf(20.f * uc, uc, fmaf(2.f * uc, S, Q));
    }
    __shared__ float sh[256], sh2[256];
    sh[t] = s; sh2[t] = s2;
    __syncthreads();
    if (t < C) {
        float S = sh[t], S2 = sh2[t];
        #pragma unroll
        for (int gg = 1; gg < G; gg++) { S += sh[gg * C + t]; S2 += sh2[gg * C + t]; }
        g_part[blockIdx.x * (2 * C) + t] = S;
        g_part[blockIdx.x * (2 * C) + C + t] = S2;
    }
}

template <int C>
__global__ void fin_k(const float* __restrict__ gamma, const float* __restrict__ beta) {
    int c = threadIdx.x;
    float S = 0.f, S2 = 0.f;
    for (int bk = 0; bk < STATS_BLOCKS; bk++) {
        S += g_part[bk * 2 * C + c];
        S2 += g_part[bk * 2 * C + C + c];
    }
    const float inv = 1.f / (float)EDG;
    float mu = S * inv;
    float var = S2 * inv - mu * mu;
    float sc = gamma[c] * rsqrtf(var + 1e-5f);
    g_scale[c] = sc;
    g_shift[c] = beta[c] - mu * sc;
}

// ---------------- finish: h = leaky(scale*(u + vmax/vmin) + shift) -----------
template <int C>
__global__ void finish_k() {
    int gid = blockIdx.x * 256 + threadIdx.x;    // NPTS*C
    int c = gid & (C - 1);
    float sc = g_scale[c];
    float vm = (sc >= 0.f) ? g_vmax[gid] : g_vmin[gid];
    float M = g_u[gid] + vm;
    float* out = (C == 64) ? (float*)g_h0 : (float*)g_h1;
    out[gid] = leaky(fmaf(M, sc, g_shift[c]));
}

// ---------------- attention gate + softmax -----------------------------------
__global__ void gate_k(const float* __restrict__ Wg, const float* __restrict__ bg) {
    int gt = blockIdx.x * 256 + threadIdx.x;
    int r = gt >> 5, lane = gt & 31;
    if (r >= NPTS) return;
    const float* h = g_h1 + (size_t)r * 256;
    float s = 0.f;
    #pragma unroll
    for (int q = 0; q < 8; q++) {
        int d = lane + (q << 5);
        s = fmaf(h[d], Wg[d], s);
    }
    #pragma unroll
    for (int o = 16; o; o >>= 1) s += __shfl_down_sync(0xffffffffu, s, o);
    if (lane == 0) {
        float gg = s + bg[0];
        g_gate[r] = gg > 0.f ? gg : 0.f;
    }
}

__global__ void softmax_k() {
    int b = blockIdx.x, t = threadIdx.x;
    __shared__ float sh[256];
    const float* gp = g_gate + (b << 12);
    float* ap = g_alpha + (b << 12);
    float mx = -FINF;
    for (int s = 0; s < 16; s++) mx = fmaxf(mx, gp[t + (s << 8)]);
    sh[t] = mx; __syncthreads();
    for (int o = 128; o; o >>= 1) { if (t < o) sh[t] = fmaxf(sh[t], sh[t + o]); __syncthreads(); }
    float M = sh[0];
    __syncthreads();
    float sum = 0.f;
    for (int s = 0; s < 16; s++) {
        int j = t + (s << 8);
        float e = expf(gp[j] - M);
        ap[j] = e;
        sum += e;
    }
    sh[t] = sum; __syncthreads();
    for (int o = 128; o; o >>= 1) { if (t < o) sh[t] += sh[t + o]; __syncthreads(); }
    float inv = 1.f / sh[0];
    for (int s = 0; s < 16; s++) ap[t + (s << 8)] *= inv;
}

// ---------------- fused feat GEMM + weighted pooling --------------------------
__global__ __launch_bounds__(256) void pool_k(const float* __restrict__ Wf,
                                              const float* __restrict__ bf) {
    int b = blockIdx.x;
    int t = threadIdx.x;
    int ch = blockIdx.y * 256 + t;
    int slab = blockIdx.z;
    __shared__ float hr[16][256];
    __shared__ float al[16];
    float acc = 0.f;
    float bfc = bf[ch];
    for (int gidx = 0; gidx < 8; gidx++) {
        int nb = (slab << 7) + (gidx << 4);
        __syncthreads();
        #pragma unroll
        for (int s = 0; s < 16; s++)
            hr[s][t] = g_h1[((size_t)(b << 12) + nb + s) * 256 + t];
        if (t < 16) al[t] = g_alpha[(b << 12) + nb + t];
        __syncthreads();
        float sacc[16];
        #pragma unroll
        for (int r = 0; r < 16; r++) sacc[r] = bfc;
        #pragma unroll 4
        for (int d = 0; d < 256; d += 4) {
            float w0 = Wf[(d + 0) * 512 + ch];
            float w1 = Wf[(d + 1) * 512 + ch];
            float w2 = Wf[(d + 2) * 512 + ch];
            float w3 = Wf[(d + 3) * 512 + ch];
            #pragma unroll
            for (int r = 0; r < 16; r++) {
                float4 hv = *(const float4*)&hr[r][d];
                sacc[r] = fmaf(hv.x, w0, fmaf(hv.y, w1, fmaf(hv.z, w2, fmaf(hv.w, w3, sacc[r]))));
            }
        }
        #pragma unroll
        for (int r = 0; r < 16; r++) {
            float f = sacc[r] > 0.f ? sacc[r] : 0.f;
            acc = fmaf(al[r], f, acc);
        }
    }
    g_pool[((slab << 2) + b) * 512 + ch] = acc;
}

__global__ void poolred_k() {
    int gid = blockIdx.x * 256 + threadIdx.x;  // BB*512
    if (gid >= BB * 512) return;
    int b = gid >> 9, ch = gid & 511;
    float s = 0.f;
    for (int sl = 0; sl < 32; sl++) s += g_pool[((sl << 2) + b) * 512 + ch];
    g_pooled[gid] = s;
}

__global__ void final_k(const float* __restrict__ Wl, const float* __restrict__ bl,
                        float* __restrict__ out) {
    int b = blockIdx.x, o = threadIdx.x;
    const float* p = g_pooled + b * 512;
    float s = bl[o];
    #pragma unroll 8
    for (int f = 0; f < 512; f++) s = fmaf(p[f], Wl[f * 256 + o], s);
    out[b * 256 + o] = s;
}

// ---------------- launch ------------------------------------------------------
extern "C" void kernel_launch(void* const* d_in, const int* in_sizes, int n_in,
                              void* d_out, int out_size) {
    (void)in_sizes; (void)n_in; (void)out_size;
    const float* x   = (const float*)d_in[0];
    const float* Wt0 = (const float*)d_in[1];
    const float* Wp0 = (const float*)d_in[3];
    const float* g0  = (const float*)d_in[5];
    const float* be0 = (const float*)d_in[6];
    const float* Wt1 = (const float*)d_in[7];
    const float* Wp1 = (const float*)d_in[9];
    const float* g1  = (const float*)d_in[11];
    const float* be1 = (const float*)d_in[12];
    const float* Wg  = (const float*)d_in[13];
    const float* bg  = (const float*)d_in[14];
    const float* Wf  = (const float*)d_in[15];
    const float* bf  = (const float*)d_in[16];
    const float* Wl  = (const float*)d_in[17];
    const float* bl  = (const float*)d_in[18];
    float* out = (float*)d_out;

    // ---- layer 0 ----
    prep_k<<<65, 256>>>(Wt0, Wp0, Wt1, Wp1);
    pack3_k<<<64, 256>>>(x);
    uv0_k<<<NPTS * 64 / 256, 256>>>(x, Wt0);
    knn0_k<<<NPTS, 256>>>();
    gather_k<64><<<STATS_BLOCKS, 256>>>();
    fin_k<64><<<1, 64>>>(g0, be0);
    finish_k<64><<<NPTS * 64 / 256, 256>>>();

    // ---- layer 1 ----
    norms64_k<<<NPTS * 32 / 256, 256>>>();
    gemm16_k<<<NPTS / 16, 256>>>(Wt1);
    dist_gemm_k<<<dim3(2080, BB), 256>>>();
    knn1_k<<<NPTS, 256>>>();
    gather_k<256><<<STATS_BLOCKS, 256>>>();
    fin_k<256><<<1, 256>>>(g1, be1);
    finish_k<256><<<NPTS * 256 / 256, 256>>>();

    // ---- attention pooling + final linear ----
    gate_k<<<NPTS * 32 / 256, 256>>>(Wg, bg);
    softmax_k<<<BB, 256>>>();
    pool_k<<<dim3(BB, 2, 32), 256>>>(Wf, bf);
    poolred_k<<<8, 256>>>();
    final_k<<<BB, 256>>>(Wl, bl, out);
}

// round 8
// speedup vs baseline: 1.1674x; 1.0473x over previous
#include <cuda_runtime.h>
#include <math.h>

#define BB 4
#define NN 4096
#define KK 20
#define NPTS (BB*NN)            // 16384
#define EDG  (NPTS*KK)          // 327680
#define STATS_BLOCKS 512
#define FULLM 0xffffffffu

#define FINF __int_as_float(0x7f800000)
#define ULLMAX 0xFFFFFFFFFFFFFFFFULL

// ---------------- scratch (device globals; no allocations allowed) ----------
__device__ unsigned g_distk[(size_t)BB * NN * NN];  // order-keys of distances (layer 1)
__device__ float4 g_x4[NPTS];                        // packed (x,y,z,|x|^2)
__device__ float g_d2[NPTS];
__device__ int   g_idx[NPTS * KK];
__device__ float g_u[NPTS * 256];
__device__ float g_v[NPTS * 256];
__device__ float g_vmax[NPTS * 256];
__device__ float g_vmin[NPTS * 256];
__device__ float g_h0[NPTS * 64];
__device__ float g_h1[NPTS * 256];
__device__ float g_Wd0[3 * 64];
__device__ float g_Wd1[64 * 256];
__device__ float g_part[STATS_BLOCKS * 2 * 256];
__device__ float g_scale[256];
__device__ float g_shift[256];
__device__ float g_gate[NPTS];
__device__ float g_alpha[NPTS];
__device__ float g_pool[32 * BB * 512];
__device__ float g_pooled[BB * 512];

static __device__ __forceinline__ float leaky(float v) { return v > 0.f ? v : 0.2f * v; }

// float -> order-preserving uint (ascending float == ascending uint)
static __device__ __forceinline__ unsigned okey(float f) {
    unsigned u = __float_as_uint(f);
    return u ^ ((unsigned)(((int)u) >> 31) | 0x80000000u);
}

// ---------------- warp streaming top-32 maintenance --------------------------
static __device__ __forceinline__ unsigned long long wmax64(unsigned long long m) {
    #pragma unroll
    for (int o = 16; o; o >>= 1) {
        unsigned long long ov = __shfl_xor_sync(FULLM, m, o);
        m = m > ov ? m : ov;
    }
    return m;
}

// maintain 32 smallest composites across the warp; sc = this lane's slot, tau = max slot
static __device__ __forceinline__ void winsert(unsigned long long c,
                                               unsigned long long& sc,
                                               unsigned long long& tau,
                                               int lane) {
    unsigned bal = __ballot_sync(FULLM, c < tau);
    while (bal) {
        int src = __ffs(bal) - 1;
        bal &= bal - 1;
        unsigned long long cn = __shfl_sync(FULLM, c, src);
        if (cn < tau) {
            unsigned eq = __ballot_sync(FULLM, sc == tau);
            if (lane == __ffs(eq) - 1) sc = cn;
            tau = wmax64(sc);
        }
    }
}

// in-register warp bitonic sort (ascending), then lanes 0..KK-1 emit indices
static __device__ __forceinline__ void wfinish(unsigned long long sc, int lane, int* out) {
    #pragma unroll
    for (int kk = 2; kk <= 32; kk <<= 1) {
        #pragma unroll
        for (int j = kk >> 1; j > 0; j >>= 1) {
            unsigned long long other = __shfl_xor_sync(FULLM, sc, j);
            bool asc = ((lane & kk) == 0);
            bool lower = ((lane & j) == 0);
            bool keepmin = (asc == lower);
            unsigned long long mn = sc < other ? sc : other;
            unsigned long long mx = sc > other ? sc : other;
            sc = keepmin ? mn : mx;
        }
    }
    if (lane < KK) out[lane] = (int)(sc & 0xffffffffu);
}

// ---------------- weight prep: Wd = Wp - Wt ---------------------------------
__global__ void prep_k(const float* __restrict__ Wt0, const float* __restrict__ Wp0,
                       const float* __restrict__ Wt1, const float* __restrict__ Wp1) {
    int i = blockIdx.x * 256 + threadIdx.x;
    if (i < 192) g_Wd0[i] = Wp0[i] - Wt0[i];
    int j = i - 192;
    if (j >= 0 && j < 16384) g_Wd1[j] = Wp1[j] - Wt1[j];
}

// ---------------- pack x + squared norm --------------------------------------
__global__ void pack3_k(const float* __restrict__ x) {
    int r = blockIdx.x * blockDim.x + threadIdx.x;
    if (r >= NPTS) return;
    float a = x[r * 3], b = x[r * 3 + 1], c = x[r * 3 + 2];
    g_x4[r] = make_float4(a, b, c, a * a + b * b + c * c);
}

__global__ void norms64_k() {
    int gt = blockIdx.x * blockDim.x + threadIdx.x;
    int r = gt >> 5, lane = gt & 31;
    if (r >= NPTS) return;
    const float* h = g_h0 + (size_t)r * 64;
    float a = h[lane], b = h[lane + 32];
    float s = a * a + b * b;
    #pragma unroll
    for (int o = 16; o; o >>= 1) s += __shfl_down_sync(FULLM, s, o);
    if (lane == 0) g_d2[r] = s;
}

// ---------------- layer0 u/v (3->64, trivial) --------------------------------
__global__ void uv0_k(const float* __restrict__ x, const float* __restrict__ Wt0) {
    int gid = blockIdx.x * 256 + threadIdx.x;   // NPTS*64 total
    int r = gid >> 6, c = gid & 63;
    float x0 = x[r * 3], x1 = x[r * 3 + 1], x2 = x[r * 3 + 2];
    g_u[gid] = x0 * Wt0[c] + x1 * Wt0[64 + c] + x2 * Wt0[128 + c];
    g_v[gid] = x0 * g_Wd0[c] + x1 * g_Wd0[64 + c] + x2 * g_Wd0[128 + c];
}

// ---------------- fused 16-row (64->256) GEMM: u1 = h0@Wt1, v1 = h0@Wd1 ------
__global__ __launch_bounds__(256) void gemm16_k(const float* __restrict__ Wt1) {
    __shared__ float hs[16 * 64];
    int r0 = blockIdx.x * 16;
    int t = threadIdx.x;
    #pragma unroll
    for (int s = 0; s < 4; s++) {
        int l = t + (s << 8);
        hs[l] = g_h0[(size_t)r0 * 64 + l];
    }
    __syncthreads();
    float au[16], av[16];
    #pragma unroll
    for (int r = 0; r < 16; r++) { au[r] = 0.f; av[r] = 0.f; }
    #pragma unroll 4
    for (int d = 0; d < 64; d++) {
        float wu = Wt1[d * 256 + t];
        float wv = g_Wd1[d * 256 + t];
        #pragma unroll
        for (int r = 0; r < 16; r++) {
            float h = hs[r * 64 + d];
            au[r] = fmaf(h, wu, au[r]);
            av[r] = fmaf(h, wv, av[r]);
        }
    }
    #pragma unroll
    for (int r = 0; r < 16; r++) {
        g_u[(size_t)(r0 + r) * 256 + t] = au[r];
        g_v[(size_t)(r0 + r) * 256 + t] = av[r];
    }
}

// ---------------- distance GEMM (layer1), triangular grid, key output --------
static __device__ __forceinline__ int tri_start(int ti) {
    return ti * 64 - (ti * (ti - 1)) / 2;
}

__global__ __launch_bounds__(256) void dist_gemm_k() {
    const int b = blockIdx.y;
    int l = blockIdx.x;                    // 0..2079
    int ti = (int)((129.0f - sqrtf(129.0f * 129.0f - 8.0f * (float)l)) * 0.5f);
    if (ti > 63) ti = 63;
    while (ti < 63 && tri_start(ti + 1) <= l) ti++;
    while (ti > 0 && tri_start(ti) > l) ti--;
    int tj = ti + (l - tri_start(ti));
    const int i0 = ti * 64, j0 = tj * 64;
    __shared__ float As[64][65];
    __shared__ float Bs[64][65];
    const float* hb = g_h0 + (size_t)b * NN * 64;
    int t = threadIdx.x;
    #pragma unroll
    for (int s = 0; s < 16; s++) {
        int ll = t + (s << 8);
        int r = ll >> 6, d = ll & 63;
        As[d][r] = hb[(size_t)(i0 + r) * 64 + d];
        Bs[d][r] = hb[(size_t)(j0 + r) * 64 + d];
    }
    __syncthreads();
    int tx = t & 15, ty = t >> 4;
    float acc[4][4];
    #pragma unroll
    for (int r = 0; r < 4; r++)
        #pragma unroll
        for (int c = 0; c < 4; c++) acc[r][c] = 0.f;
    #pragma unroll 8
    for (int d = 0; d < 64; d++) {
        float a0 = As[d][ty * 4 + 0], a1 = As[d][ty * 4 + 1];
        float a2 = As[d][ty * 4 + 2], a3 = As[d][ty * 4 + 3];
        float b0 = Bs[d][tx * 4 + 0], b1 = Bs[d][tx * 4 + 1];
        float b2 = Bs[d][tx * 4 + 2], b3 = Bs[d][tx * 4 + 3];
        acc[0][0] = fmaf(a0, b0, acc[0][0]); acc[0][1] = fmaf(a0, b1, acc[0][1]);
        acc[0][2] = fmaf(a0, b2, acc[0][2]); acc[0][3] = fmaf(a0, b3, acc[0][3]);
        acc[1][0] = fmaf(a1, b0, acc[1][0]); acc[1][1] = fmaf(a1, b1, acc[1][1]);
        acc[1][2] = fmaf(a1, b2, acc[1][2]); acc[1][3] = fmaf(a1, b3, acc[1][3]);
        acc[2][0] = fmaf(a2, b0, acc[2][0]); acc[2][1] = fmaf(a2, b1, acc[2][1]);
        acc[2][2] = fmaf(a2, b2, acc[2][2]); acc[2][3] = fmaf(a2, b3, acc[2][3]);
        acc[3][0] = fmaf(a3, b0, acc[3][0]); acc[3][1] = fmaf(a3, b1, acc[3][1]);
        acc[3][2] = fmaf(a3, b2, acc[3][2]); acc[3][3] = fmaf(a3, b3, acc[3][3]);
    }
    const float* n2 = g_d2 + b * NN;
    float nj0 = n2[j0 + tx * 4 + 0], nj1 = n2[j0 + tx * 4 + 1];
    float nj2 = n2[j0 + tx * 4 + 2], nj3 = n2[j0 + tx * 4 + 3];
    unsigned kv[4][4];
    #pragma unroll
    for (int r = 0; r < 4; r++) {
        float ni = n2[i0 + ty * 4 + r];
        kv[r][0] = okey(ni + nj0 - 2.f * acc[r][0]);
        kv[r][1] = okey(ni + nj1 - 2.f * acc[r][1]);
        kv[r][2] = okey(ni + nj2 - 2.f * acc[r][2]);
        kv[r][3] = okey(ni + nj3 - 2.f * acc[r][3]);
        *(uint4*)&g_distk[((size_t)(b * NN + i0 + ty * 4 + r)) * NN + j0 + tx * 4] =
            make_uint4(kv[r][0], kv[r][1], kv[r][2], kv[r][3]);
    }
    if (ti != tj) {
        __syncthreads();
        unsigned* Ts = (unsigned*)&As[0][0];   // reuse [64][65]
        #pragma unroll
        for (int r = 0; r < 4; r++)
            #pragma unroll
            for (int c = 0; c < 4; c++)
                Ts[(tx * 4 + c) * 65 + (ty * 4 + r)] = kv[r][c];
        __syncthreads();
        #pragma unroll
        for (int s = 0; s < 16; s++) {
            int ll = t + (s << 8);
            int jr = ll >> 6, ic = ll & 63;
            g_distk[((size_t)(b * NN + j0 + jr)) * NN + i0 + ic] = Ts[jr * 65 + ic];
        }
    }
}

// ---------------- knn0: warp-per-row streaming select, smem point tiles ------
__global__ __launch_bounds__(256) void knn0_k() {
    __shared__ float4 pts[1024];               // 16 KB tile shared by 8 warps
    int t = threadIdx.x;
    int w = t >> 5, lane = t & 31;
    int row = blockIdx.x * 8 + w;
    int base = row & ~(NN - 1);
    float4 me = g_x4[row];

    unsigned long long sc = ULLMAX, tau = ULLMAX;
    #pragma unroll 1
    for (int chunk = 0; chunk < 4; chunk++) {
        __syncthreads();
        #pragma unroll
        for (int i = 0; i < 4; i++)
            pts[t + (i << 8)] = g_x4[base + (chunk << 10) + t + (i << 8)];
        __syncthreads();
        #pragma unroll 1
        for (int it = 0; it < 32; it++) {
            int jl = (it << 5) + lane;
            float4 p = pts[jl];
            float dot = me.x * p.x + me.y * p.y + me.z * p.z;
            unsigned key = okey(me.w + p.w - 2.f * dot);
            unsigned long long c =
                ((unsigned long long)key << 32) | (unsigned)((chunk << 10) + jl);
            if (chunk == 0 && it == 0) {       // init: fill 32 slots directly
                sc = c;
                tau = wmax64(sc);
            } else {
                winsert(c, sc, tau, lane);
            }
        }
    }
    wfinish(sc, lane, g_idx + row * KK);
}

// ---------------- knn1: warp-per-row streaming select over key rows ----------
__global__ __launch_bounds__(256) void knn1_k() {
    int t = threadIdx.x;
    int w = t >> 5, lane = t & 31;
    int row = blockIdx.x * 8 + w;
    const unsigned* dr = g_distk + (size_t)row * NN;

    unsigned long long sc, tau;
    {
        unsigned key = dr[lane];
        sc = ((unsigned long long)key << 32) | (unsigned)lane;
        tau = wmax64(sc);
    }
    #pragma unroll 1
    for (int it = 1; it < 128; it++) {
        int j = (it << 5) + lane;
        unsigned key = __ldg(&dr[j]);
        unsigned long long c = ((unsigned long long)key << 32) | (unsigned)j;
        winsert(c, sc, tau, lane);
    }
    wfinish(sc, lane, g_idx + row * KK);
}

// ---------------- fused gather: BN stats + per-point neighbor vmax/vmin ------
template <int C>
__global__ __launch_bounds__(256) void gather_k() {
    constexpr int G = 256 / C;
    int t = threadIdx.x;
    int c = t % C;
    int g = t / C;
    float s = 0.f, s2 = 0.f;
    for (int p = blockIdx.x * G + g; p < NPTS; p += STATS_BLOCKS * G) {
        int b = p >> 12;
        float uc = g_u[(size_t)p * C + c];
        const int* ip = g_idx + p * KK;
        float S = 0.f, Q = 0.f, mx = -FINF, mn = FINF;
        #pragma unroll
        for (int k = 0; k < KK; k++) {
            int j = ip[k];
            float v = g_v[((size_t)((b << 12) + j)) * C + c];
            S += v;
            Q = fmaf(v, v, Q);
            mx = fmaxf(mx, v);
            mn = fminf(mn, v);
        }
        g_vmax[(size_t)p * C + c] = mx;
        g_vmin[(size_t)p * C + c] = mn;
        s += fmaf(20.f, uc, S);
        s2 += fmaf(20.f * uc, uc, fmaf(2.f * uc, S, Q));
    }
    __shared__ float sh[256], sh2[256];
    sh[t] = s; sh2[t] = s2;
    __syncthreads();
    if (t < C) {
        float S = sh[t], S2 = sh2[t];
        #pragma unroll
        for (int gg = 1; gg < G; gg++) { S += sh[gg * C + t]; S2 += sh2[gg * C + t]; }
        g_part[blockIdx.x * (2 * C) + t] = S;
        g_part[blockIdx.x * (2 * C) + C + t] = S2;
    }
}

template <int C>
__global__ void fin_k(const float* __restrict__ gamma, const float* __restrict__ beta) {
    int c = threadIdx.x;
    float S = 0.f, S2 = 0.f;
    for (int bk = 0; bk < STATS_BLOCKS; bk++) {
        S += g_part[bk * 2 * C + c];
        S2 += g_part[bk * 2 * C + C + c];
    }
    const float inv = 1.f / (float)EDG;
    float mu = S * inv;
    float var = S2 * inv - mu * mu;
    float sc = gamma[c] * rsqrtf(var + 1e-5f);
    g_scale[c] = sc;
    g_shift[c] = beta[c] - mu * sc;
}

// ---------------- finish: h = leaky(scale*(u + vmax/vmin) + shift) -----------
template <int C>
__global__ void finish_k() {
    int gid = blockIdx.x * 256 + threadIdx.x;    // NPTS*C
    int c = gid & (C - 1);
    float sc = g_scale[c];
    float vm = (sc >= 0.f) ? g_vmax[gid] : g_vmin[gid];
    float M = g_u[gid] + vm;
    float* out = (C == 64) ? (float*)g_h0 : (float*)g_h1;
    out[gid] = leaky(fmaf(M, sc, g_shift[c]));
}

// ---------------- attention gate + softmax -----------------------------------
__global__ void gate_k(const float* __restrict__ Wg, const float* __restrict__ bg) {
    int gt = blockIdx.x * 256 + threadIdx.x;
    int r = gt >> 5, lane = gt & 31;
    if (r >= NPTS) return;
    const float* h = g_h1 + (size_t)r * 256;
    float s = 0.f;
    #pragma unroll
    for (int q = 0; q < 8; q++) {
        int d = lane + (q << 5);
        s = fmaf(h[d], Wg[d], s);
    }
    #pragma unroll
    for (int o = 16; o; o >>= 1) s += __shfl_down_sync(FULLM, s, o);
    if (lane == 0) {
        float gg = s + bg[0];
        g_gate[r] = gg > 0.f ? gg : 0.f;
    }
}

__global__ void softmax_k() {
    int b = blockIdx.x, t = threadIdx.x;
    __shared__ float sh[256];
    const float* gp = g_gate + (b << 12);
    float* ap = g_alpha + (b << 12);
    float mx = -FINF;
    for (int s = 0; s < 16; s++) mx = fmaxf(mx, gp[t + (s << 8)]);
    sh[t] = mx; __syncthreads();
    for (int o = 128; o; o >>= 1) { if (t < o) sh[t] = fmaxf(sh[t], sh[t + o]); __syncthreads(); }
    float M = sh[0];
    __syncthreads();
    float sum = 0.f;
    for (int s = 0; s < 16; s++) {
        int j = t + (s << 8);
        float e = expf(gp[j] - M);
        ap[j] = e;
        sum += e;
    }
    sh[t] = sum; __syncthreads();
    for (int o = 128; o; o >>= 1) { if (t < o) sh[t] += sh[t + o]; __syncthreads(); }
    float inv = 1.f / sh[0];
    for (int s = 0; s < 16; s++) ap[t + (s << 8)] *= inv;
}

// ---------------- fused feat GEMM + weighted pooling --------------------------
__global__ __launch_bounds__(256) void pool_k(const float* __restrict__ Wf,
                                              const float* __restrict__ bf) {
    int b = blockIdx.x;
    int t = threadIdx.x;
    int ch = blockIdx.y * 256 + t;
    int slab = blockIdx.z;
    __shared__ float hr[16][256];
    __shared__ float al[16];
    float acc = 0.f;
    float bfc = bf[ch];
    for (int gidx = 0; gidx < 8; gidx++) {
        int nb = (slab << 7) + (gidx << 4);
        __syncthreads();
        #pragma unroll
        for (int s = 0; s < 16; s++)
            hr[s][t] = g_h1[((size_t)(b << 12) + nb + s) * 256 + t];
        if (t < 16) al[t] = g_alpha[(b << 12) + nb + t];
        __syncthreads();
        float sacc[16];
        #pragma unroll
        for (int r = 0; r < 16; r++) sacc[r] = bfc;
        #pragma unroll 4
        for (int d = 0; d < 256; d += 4) {
            float w0 = Wf[(d + 0) * 512 + ch];
            float w1 = Wf[(d + 1) * 512 + ch];
            float w2 = Wf[(d + 2) * 512 + ch];
            float w3 = Wf[(d + 3) * 512 + ch];
            #pragma unroll
            for (int r = 0; r < 16; r++) {
                float4 hv = *(const float4*)&hr[r][d];
                sacc[r] = fmaf(hv.x, w0, fmaf(hv.y, w1, fmaf(hv.z, w2, fmaf(hv.w, w3, sacc[r]))));
            }
        }
        #pragma unroll
        for (int r = 0; r < 16; r++) {
            float f = sacc[r] > 0.f ? sacc[r] : 0.f;
            acc = fmaf(al[r], f, acc);
        }
    }
    g_pool[((slab << 2) + b) * 512 + ch] = acc;
}

__global__ void poolred_k() {
    int gid = blockIdx.x * 256 + threadIdx.x;  // BB*512
    if (gid >= BB * 512) return;
    int b = gid >> 9, ch = gid & 511;
    float s = 0.f;
    for (int sl = 0; sl < 32; sl++) s += g_pool[((sl << 2) + b) * 512 + ch];
    g_pooled[gid] = s;
}

__global__ void final_k(const float* __restrict__ Wl, const float* __restrict__ bl,
                        float* __restrict__ out) {
    int b = blockIdx.x, o = threadIdx.x;
    const float* p = g_pooled + b * 512;
    float s = bl[o];
    #pragma unroll 8
    for (int f = 0; f < 512; f++) s = fmaf(p[f], Wl[f * 256 + o], s);
    out[b * 256 + o] = s;
}

// ---------------- launch ------------------------------------------------------
extern "C" void kernel_launch(void* const* d_in, const int* in_sizes, int n_in,
                              void* d_out, int out_size) {
    (void)in_sizes; (void)n_in; (void)out_size;
    const float* x   = (const float*)d_in[0];
    const float* Wt0 = (const float*)d_in[1];
    const float* Wp0 = (const float*)d_in[3];
    const float* g0  = (const float*)d_in[5];
    const float* be0 = (const float*)d_in[6];
    const float* Wt1 = (const float*)d_in[7];
    const float* Wp1 = (const float*)d_in[9];
    const float* g1  = (const float*)d_in[11];
    const float* be1 = (const float*)d_in[12];
    const float* Wg  = (const float*)d_in[13];
    const float* bg  = (const float*)d_in[14];
    const float* Wf  = (const float*)d_in[15];
    const float* bf  = (const float*)d_in[16];
    const float* Wl  = (const float*)d_in[17];
    const float* bl  = (const float*)d_in[18];
    float* out = (float*)d_out;

    // ---- layer 0 ----
    prep_k<<<65, 256>>>(Wt0, Wp0, Wt1, Wp1);
    pack3_k<<<64, 256>>>(x);
    uv0_k<<<NPTS * 64 / 256, 256>>>(x, Wt0);
    knn0_k<<<NPTS / 8, 256>>>();
    gather_k<64><<<STATS_BLOCKS, 256>>>();
    fin_k<64><<<1, 64>>>(g0, be0);
    finish_k<64><<<NPTS * 64 / 256, 256>>>();

    // ---- layer 1 ----
    norms64_k<<<NPTS * 32 / 256, 256>>>();
    gemm16_k<<<NPTS / 16, 256>>>(Wt1);
    dist_gemm_k<<<dim3(2080, BB), 256>>>();
    knn1_k<<<NPTS / 8, 256>>>();
    gather_k<256><<<STATS_BLOCKS, 256>>>();
    fin_k<256><<<1, 256>>>(g1, be1);
    finish_k<256><<<NPTS * 256 / 256, 256>>>();

    // ---- attention pooling + final linear ----
    gate_k<<<NPTS * 32 / 256, 256>>>(Wg, bg);
    softmax_k<<<BB, 256>>>();
    pool_k<<<dim3(BB, 2, 32), 256>>>(Wf, bf);
    poolred_k<<<8, 256>>>();
    final_k<<<BB, 256>>>(Wl, bl, out);
}

// round 9
// speedup vs baseline: 1.5246x; 1.3060x over previous
#include <cuda_runtime.h>
#include <math.h>

#define BB 4
#define NN 4096
#define KK 20
#define NPTS (BB*NN)            // 16384
#define EDG  (NPTS*KK)          // 327680
#define STATS_BLOCKS 512
#define FULLM 0xffffffffu

#define FINF __int_as_float(0x7f800000)
#define ULLMAX 0xFFFFFFFFFFFFFFFFULL

// ---------------- scratch (device globals; no allocations allowed) ----------
__device__ unsigned g_distk[(size_t)BB * NN * NN];  // order-keys of distances (layer 1)
__device__ float4 g_x4[NPTS];                        // packed (x,y,z,|x|^2)
__device__ float g_d2[NPTS];
__device__ int   g_idx[NPTS * KK];
__device__ float g_u[NPTS * 256];
__device__ float g_v[NPTS * 256];
__device__ float g_vmax[NPTS * 256];
__device__ float g_vmin[NPTS * 256];
__device__ float g_h0[NPTS * 64];
__device__ float g_h1[NPTS * 256];
__device__ float g_Wd0[3 * 64];
__device__ float g_Wd1[64 * 256];
__device__ float g_part[STATS_BLOCKS * 2 * 256];
__device__ float g_scale[256];
__device__ float g_shift[256];
__device__ float g_gate[NPTS];
__device__ float g_alpha[NPTS];
__device__ float g_pool[32 * BB * 512];
__device__ float g_pooled[BB * 512];

static __device__ __forceinline__ float leaky(float v) { return v > 0.f ? v : 0.2f * v; }

// float -> order-preserving uint (ascending float == ascending uint)
static __device__ __forceinline__ unsigned okey(float f) {
    unsigned u = __float_as_uint(f);
    return u ^ ((unsigned)(((int)u) >> 31) | 0x80000000u);
}

// ---------------- warp bitonic sort of NR*32 u64 (ascending by position) -----
// position p = rr*32 + lane; v[rr] holds element at p.
template <int NR>
static __device__ __forceinline__ void wsortu64(unsigned long long* v, int lane) {
    const int N = NR * 32;
    #pragma unroll
    for (int k = 2; k <= N; k <<= 1) {
        #pragma unroll
        for (int j = k >> 1; j > 0; j >>= 1) {
            if (j >= 32) {
                int rj = j >> 5;
                #pragma unroll
                for (int rr = 0; rr < NR; rr++) {
                    int pr = rr ^ rj;
                    if (pr > rr) {
                        int p = rr * 32 + lane;
                        bool asc = ((p & k) == 0);
                        unsigned long long a = v[rr], b = v[pr];
                        unsigned long long mn = a < b ? a : b;
                        unsigned long long mx = a < b ? b : a;
                        v[rr] = asc ? mn : mx;
                        v[pr] = asc ? mx : mn;
                    }
                }
            } else {
                #pragma unroll
                for (int rr = 0; rr < NR; rr++) {
                    int p = rr * 32 + lane;
                    bool asc = ((p & k) == 0);
                    bool lower = ((lane & j) == 0);
                    unsigned long long o = __shfl_xor_sync(FULLM, v[rr], j);
                    bool keepmin = (asc == lower);
                    unsigned long long mn = v[rr] < o ? v[rr] : o;
                    unsigned long long mx = v[rr] < o ? o : v[rr];
                    v[rr] = keepmin ? mn : mx;
                }
            }
        }
    }
}

// ---------------- fallback streaming top-32 (exact, rare) --------------------
static __device__ __forceinline__ unsigned long long wmax64(unsigned long long m) {
    #pragma unroll
    for (int o = 16; o; o >>= 1) {
        unsigned long long ov = __shfl_xor_sync(FULLM, m, o);
        m = m > ov ? m : ov;
    }
    return m;
}

static __device__ __forceinline__ void winsert(unsigned long long c,
                                               unsigned long long& sc,
                                               unsigned long long& tau,
                                               int lane) {
    unsigned bal = __ballot_sync(FULLM, c < tau);
    while (bal) {
        int src = __ffs(bal) - 1;
        bal &= bal - 1;
        unsigned long long cn = __shfl_sync(FULLM, c, src);
        if (cn < tau) {
            unsigned eq = __ballot_sync(FULLM, sc == tau);
            if (lane == __ffs(eq) - 1) sc = cn;
            tau = wmax64(sc);
        }
    }
}

static __device__ __forceinline__ void wfinish(unsigned long long sc, int lane, int* out) {
    unsigned long long v1[1] = {sc};
    // full 32-sort via the shared routine (NR=1)
    #pragma unroll
    for (int k = 2; k <= 32; k <<= 1) {
        #pragma unroll
        for (int j = k >> 1; j > 0; j >>= 1) {
            bool asc = ((lane & k) == 0);
            bool lower = ((lane & j) == 0);
            unsigned long long o = __shfl_xor_sync(FULLM, v1[0], j);
            bool keepmin = (asc == lower);
            unsigned long long mn = v1[0] < o ? v1[0] : o;
            unsigned long long mx = v1[0] < o ? o : v1[0];
            v1[0] = keepmin ? mn : mx;
        }
    }
    if (lane < KK) out[lane] = (int)(v1[0] & 0xffffffffu);
}

// ---------------- weight prep: Wd = Wp - Wt ---------------------------------
__global__ void prep_k(const float* __restrict__ Wt0, const float* __restrict__ Wp0,
                       const float* __restrict__ Wt1, const float* __restrict__ Wp1) {
    int i = blockIdx.x * 256 + threadIdx.x;
    if (i < 192) g_Wd0[i] = Wp0[i] - Wt0[i];
    int j = i - 192;
    if (j >= 0 && j < 16384) g_Wd1[j] = Wp1[j] - Wt1[j];
}

// ---------------- pack x + squared norm --------------------------------------
__global__ void pack3_k(const float* __restrict__ x) {
    int r = blockIdx.x * blockDim.x + threadIdx.x;
    if (r >= NPTS) return;
    float a = x[r * 3], b = x[r * 3 + 1], c = x[r * 3 + 2];
    g_x4[r] = make_float4(a, b, c, a * a + b * b + c * c);
}

__global__ void norms64_k() {
    int gt = blockIdx.x * blockDim.x + threadIdx.x;
    int r = gt >> 5, lane = gt & 31;
    if (r >= NPTS) return;
    const float* h = g_h0 + (size_t)r * 64;
    float a = h[lane], b = h[lane + 32];
    float s = a * a + b * b;
    #pragma unroll
    for (int o = 16; o; o >>= 1) s += __shfl_down_sync(FULLM, s, o);
    if (lane == 0) g_d2[r] = s;
}

// ---------------- layer0 u/v (3->64, trivial) --------------------------------
__global__ void uv0_k(const float* __restrict__ x, const float* __restrict__ Wt0) {
    int gid = blockIdx.x * 256 + threadIdx.x;   // NPTS*64 total
    int r = gid >> 6, c = gid & 63;
    float x0 = x[r * 3], x1 = x[r * 3 + 1], x2 = x[r * 3 + 2];
    g_u[gid] = x0 * Wt0[c] + x1 * Wt0[64 + c] + x2 * Wt0[128 + c];
    g_v[gid] = x0 * g_Wd0[c] + x1 * g_Wd0[64 + c] + x2 * g_Wd0[128 + c];
}

// ---------------- fused 16-row (64->256) GEMM: u1 = h0@Wt1, v1 = h0@Wd1 ------
__global__ __launch_bounds__(256) void gemm16_k(const float* __restrict__ Wt1) {
    __shared__ float hs[16 * 64];
    int r0 = blockIdx.x * 16;
    int t = threadIdx.x;
    #pragma unroll
    for (int s = 0; s < 4; s++) {
        int l = t + (s << 8);
        hs[l] = g_h0[(size_t)r0 * 64 + l];
    }
    __syncthreads();
    float au[16], av[16];
    #pragma unroll
    for (int r = 0; r < 16; r++) { au[r] = 0.f; av[r] = 0.f; }
    #pragma unroll 4
    for (int d = 0; d < 64; d++) {
        float wu = Wt1[d * 256 + t];
        float wv = g_Wd1[d * 256 + t];
        #pragma unroll
        for (int r = 0; r < 16; r++) {
            float h = hs[r * 64 + d];
            au[r] = fmaf(h, wu, au[r]);
            av[r] = fmaf(h, wv, av[r]);
        }
    }
    #pragma unroll
    for (int r = 0; r < 16; r++) {
        g_u[(size_t)(r0 + r) * 256 + t] = au[r];
        g_v[(size_t)(r0 + r) * 256 + t] = av[r];
    }
}

// ---------------- distance GEMM (layer1), triangular grid, key output --------
static __device__ __forceinline__ int tri_start(int ti) {
    return ti * 64 - (ti * (ti - 1)) / 2;
}

__global__ __launch_bounds__(256) void dist_gemm_k() {
    const int b = blockIdx.y;
    int l = blockIdx.x;                    // 0..2079
    int ti = (int)((129.0f - sqrtf(129.0f * 129.0f - 8.0f * (float)l)) * 0.5f);
    if (ti > 63) ti = 63;
    while (ti < 63 && tri_start(ti + 1) <= l) ti++;
    while (ti > 0 && tri_start(ti) > l) ti--;
    int tj = ti + (l - tri_start(ti));
    const int i0 = ti * 64, j0 = tj * 64;
    __shared__ float As[64][65];
    __shared__ float Bs[64][65];
    const float* hb = g_h0 + (size_t)b * NN * 64;
    int t = threadIdx.x;
    #pragma unroll
    for (int s = 0; s < 16; s++) {
        int ll = t + (s << 8);
        int r = ll >> 6, d = ll & 63;
        As[d][r] = hb[(size_t)(i0 + r) * 64 + d];
        Bs[d][r] = hb[(size_t)(j0 + r) * 64 + d];
    }
    __syncthreads();
    int tx = t & 15, ty = t >> 4;
    float acc[4][4];
    #pragma unroll
    for (int r = 0; r < 4; r++)
        #pragma unroll
        for (int c = 0; c < 4; c++) acc[r][c] = 0.f;
    #pragma unroll 8
    for (int d = 0; d < 64; d++) {
        float a0 = As[d][ty * 4 + 0], a1 = As[d][ty * 4 + 1];
        float a2 = As[d][ty * 4 + 2], a3 = As[d][ty * 4 + 3];
        float b0 = Bs[d][tx * 4 + 0], b1 = Bs[d][tx * 4 + 1];
        float b2 = Bs[d][tx * 4 + 2], b3 = Bs[d][tx * 4 + 3];
        acc[0][0] = fmaf(a0, b0, acc[0][0]); acc[0][1] = fmaf(a0, b1, acc[0][1]);
        acc[0][2] = fmaf(a0, b2, acc[0][2]); acc[0][3] = fmaf(a0, b3, acc[0][3]);
        acc[1][0] = fmaf(a1, b0, acc[1][0]); acc[1][1] = fmaf(a1, b1, acc[1][1]);
        acc[1][2] = fmaf(a1, b2, acc[1][2]); acc[1][3] = fmaf(a1, b3, acc[1][3]);
        acc[2][0] = fmaf(a2, b0, acc[2][0]); acc[2][1] = fmaf(a2, b1, acc[2][1]);
        acc[2][2] = fmaf(a2, b2, acc[2][2]); acc[2][3] = fmaf(a2, b3, acc[2][3]);
        acc[3][0] = fmaf(a3, b0, acc[3][0]); acc[3][1] = fmaf(a3, b1, acc[3][1]);
        acc[3][2] = fmaf(a3, b2, acc[3][2]); acc[3][3] = fmaf(a3, b3, acc[3][3]);
    }
    const float* n2 = g_d2 + b * NN;
    float nj0 = n2[j0 + tx * 4 + 0], nj1 = n2[j0 + tx * 4 + 1];
    float nj2 = n2[j0 + tx * 4 + 2], nj3 = n2[j0 + tx * 4 + 3];
    unsigned kv[4][4];
    #pragma unroll
    for (int r = 0; r < 4; r++) {
        float ni = n2[i0 + ty * 4 + r];
        kv[r][0] = okey(ni + nj0 - 2.f * acc[r][0]);
        kv[r][1] = okey(ni + nj1 - 2.f * acc[r][1]);
        kv[r][2] = okey(ni + nj2 - 2.f * acc[r][2]);
        kv[r][3] = okey(ni + nj3 - 2.f * acc[r][3]);
        *(uint4*)&g_distk[((size_t)(b * NN + i0 + ty * 4 + r)) * NN + j0 + tx * 4] =
            make_uint4(kv[r][0], kv[r][1], kv[r][2], kv[r][3]);
    }
    if (ti != tj) {
        __syncthreads();
        unsigned* Ts = (unsigned*)&As[0][0];   // reuse [64][65]
        #pragma unroll
        for (int r = 0; r < 4; r++)
            #pragma unroll
            for (int c = 0; c < 4; c++)
                Ts[(tx * 4 + c) * 65 + (ty * 4 + r)] = kv[r][c];
        __syncthreads();
        #pragma unroll
        for (int s = 0; s < 16; s++) {
            int ll = t + (s << 8);
            int jr = ll >> 6, ic = ll & 63;
            g_distk[((size_t)(b * NN + j0 + jr)) * NN + i0 + ic] = Ts[jr * 65 + ic];
        }
    }
}

// ---------------- knn0: two-pass threshold select (smem point tiles) ---------
__global__ __launch_bounds__(256) void knn0_k() {
    __shared__ float4 pts[1024];                    // 16 KB
    __shared__ unsigned long long buf[8][128];      // 8 KB
    int t = threadIdx.x, w = t >> 5, lane = t & 31;
    int row = blockIdx.x * 8 + w;
    int base = row & ~(NN - 1);
    float4 me = g_x4[row];

    // pass 1: per-lane top-2 composites
    unsigned long long m0 = ULLMAX, m1 = ULLMAX;
    #pragma unroll 1
    for (int chunk = 0; chunk < 4; chunk++) {
        __syncthreads();
        #pragma unroll
        for (int i = 0; i < 4; i++)
            pts[t + (i << 8)] = g_x4[base + (chunk << 10) + t + (i << 8)];
        __syncthreads();
        #pragma unroll 4
        for (int it = 0; it < 32; it++) {
            int jl = (it << 5) + lane;
            float4 p = pts[jl];
            float dot = me.x * p.x + me.y * p.y + me.z * p.z;
            unsigned key = okey(me.w + p.w - 2.f * dot);
            unsigned long long c =
                ((unsigned long long)key << 32) | (unsigned)((chunk << 10) + jl);
            if (c < m0) { m1 = m0; m0 = c; }
            else if (c < m1) { m1 = c; }
        }
    }
    unsigned long long v2[2] = {m0, m1};
    wsortu64<2>(v2, lane);
    unsigned long long tauc = __shfl_sync(FULLM, v2[0], 31);  // 32nd smallest collected

    // pass 2: compact all c <= tauc
    int cnt = 0;
    #pragma unroll 1
    for (int chunk = 0; chunk < 4; chunk++) {
        __syncthreads();
        #pragma unroll
        for (int i = 0; i < 4; i++)
            pts[t + (i << 8)] = g_x4[base + (chunk << 10) + t + (i << 8)];
        __syncthreads();
        #pragma unroll 4
        for (int it = 0; it < 32; it++) {
            int jl = (it << 5) + lane;
            float4 p = pts[jl];
            float dot = me.x * p.x + me.y * p.y + me.z * p.z;
            unsigned key = okey(me.w + p.w - 2.f * dot);
            unsigned long long c =
                ((unsigned long long)key << 32) | (unsigned)((chunk << 10) + jl);
            unsigned mask = __ballot_sync(FULLM, c <= tauc);
            if (c <= tauc) {
                int pos = cnt + __popc(mask & ((1u << lane) - 1));
                if (pos < 128) buf[w][pos] = c;
            }
            cnt += __popc(mask);
        }
    }
    int* out = g_idx + row * KK;
    if (cnt <= 64) {
        unsigned long long e[2];
        e[0] = (lane < cnt) ? buf[w][lane] : ULLMAX;
        e[1] = (lane + 32 < cnt) ? buf[w][lane + 32] : ULLMAX;
        wsortu64<2>(e, lane);
        if (lane < KK) out[lane] = (int)(e[0] & 0xffffffffu);
    } else if (cnt <= 128) {
        unsigned long long e[4];
        #pragma unroll
        for (int rr = 0; rr < 4; rr++)
            e[rr] = (rr * 32 + lane < cnt) ? buf[w][rr * 32 + lane] : ULLMAX;
        wsortu64<4>(e, lane);
        if (lane < KK) out[lane] = (int)(e[0] & 0xffffffffu);
    } else {
        // degenerate ties: exact streaming fallback (global reads, no block syncs)
        unsigned long long sc, tau;
        {
            float4 p = g_x4[base + lane];
            float dot = me.x * p.x + me.y * p.y + me.z * p.z;
            unsigned key = okey(me.w + p.w - 2.f * dot);
            sc = ((unsigned long long)key << 32) | (unsigned)lane;
            tau = wmax64(sc);
        }
        for (int it = 1; it < 128; it++) {
            int j = (it << 5) + lane;
            float4 p = g_x4[base + j];
            float dot = me.x * p.x + me.y * p.y + me.z * p.z;
            unsigned key = okey(me.w + p.w - 2.f * dot);
            unsigned long long c = ((unsigned long long)key << 32) | (unsigned)j;
            winsert(c, sc, tau, lane);
        }
        wfinish(sc, lane, out);
    }
}

// ---------------- knn1: two-pass threshold select over key rows --------------
__global__ __launch_bounds__(256) void knn1_k() {
    __shared__ unsigned long long buf[8][128];      // 8 KB
    int t = threadIdx.x, w = t >> 5, lane = t & 31;
    int row = blockIdx.x * 8 + w;
    const uint4* dr = (const uint4*)(g_distk + (size_t)row * NN);   // 1024 uint4

    // pass 1
    unsigned long long m0 = ULLMAX, m1 = ULLMAX;
    #pragma unroll 4
    for (int it = 0; it < 32; it++) {
        int j4 = (it << 5) + lane;
        uint4 kv = __ldg(&dr[j4]);
        int jb = j4 << 2;
        unsigned long long c;
        c = ((unsigned long long)kv.x << 32) | (unsigned)(jb + 0);
        if (c < m0) { m1 = m0; m0 = c; } else if (c < m1) { m1 = c; }
        c = ((unsigned long long)kv.y << 32) | (unsigned)(jb + 1);
        if (c < m0) { m1 = m0; m0 = c; } else if (c < m1) { m1 = c; }
        c = ((unsigned long long)kv.z << 32) | (unsigned)(jb + 2);
        if (c < m0) { m1 = m0; m0 = c; } else if (c < m1) { m1 = c; }
        c = ((unsigned long long)kv.w << 32) | (unsigned)(jb + 3);
        if (c < m0) { m1 = m0; m0 = c; } else if (c < m1) { m1 = c; }
    }
    unsigned long long v2[2] = {m0, m1};
    wsortu64<2>(v2, lane);
    unsigned long long tauc = __shfl_sync(FULLM, v2[0], 31);

    // pass 2 (row is L1-resident)
    int cnt = 0;
    #pragma unroll 1
    for (int it = 0; it < 32; it++) {
        int j4 = (it << 5) + lane;
        uint4 kv = __ldg(&dr[j4]);
        int jb = j4 << 2;
        unsigned keys[4] = {kv.x, kv.y, kv.z, kv.w};
        #pragma unroll
        for (int q = 0; q < 4; q++) {
            unsigned long long c = ((unsigned long long)keys[q] << 32) | (unsigned)(jb + q);
            unsigned mask = __ballot_sync(FULLM, c <= tauc);
            if (c <= tauc) {
                int pos = cnt + __popc(mask & ((1u << lane) - 1));
                if (pos < 128) buf[w][pos] = c;
            }
            cnt += __popc(mask);
        }
    }
    int* out = g_idx + row * KK;
    if (cnt <= 64) {
        unsigned long long e[2];
        e[0] = (lane < cnt) ? buf[w][lane] : ULLMAX;
        e[1] = (lane + 32 < cnt) ? buf[w][lane + 32] : ULLMAX;
        wsortu64<2>(e, lane);
        if (lane < KK) out[lane] = (int)(e[0] & 0xffffffffu);
    } else if (cnt <= 128) {
        unsigned long long e[4];
        #pragma unroll
        for (int rr = 0; rr < 4; rr++)
            e[rr] = (rr * 32 + lane < cnt) ? buf[w][rr * 32 + lane] : ULLMAX;
        wsortu64<4>(e, lane);
        if (lane < KK) out[lane] = (int)(e[0] & 0xffffffffu);
    } else {
        const unsigned* drs = g_distk + (size_t)row * NN;
        unsigned long long sc, tau;
        {
            unsigned key = drs[lane];
            sc = ((unsigned long long)key << 32) | (unsigned)lane;
            tau = wmax64(sc);
        }
        for (int it = 1; it < 128; it++) {
            int j = (it << 5) + lane;
            unsigned key = __ldg(&drs[j]);
            unsigned long long c = ((unsigned long long)key << 32) | (unsigned)j;
            winsert(c, sc, tau, lane);
        }
        wfinish(sc, lane, out);
    }
}

// ---------------- fused gather: BN stats + per-point neighbor vmax/vmin ------
template <int C>
__global__ __launch_bounds__(256) void gather_k() {
    constexpr int G = 256 / C;
    int t = threadIdx.x;
    int c = t % C;
    int g = t / C;
    float s = 0.f, s2 = 0.f;
    for (int p = blockIdx.x * G + g; p < NPTS; p += STATS_BLOCKS * G) {
        int b = p >> 12;
        float uc = g_u[(size_t)p * C + c];
        const int* ip = g_idx + p * KK;
        float S = 0.f, Q = 0.f, mx = -FINF, mn = FINF;
        #pragma unroll
        for (int k = 0; k < KK; k++) {
            int j = ip[k];
            float v = g_v[((size_t)((b << 12) + j)) * C + c];
            S += v;
            Q = fmaf(v, v, Q);
            mx = fmaxf(mx, v);
            mn = fminf(mn, v);
        }
        g_vmax[(size_t)p * C + c] = mx;
        g_vmin[(size_t)p * C + c] = mn;
        s += fmaf(20.f, uc, S);
        s2 += fmaf(20.f * uc, uc, fmaf(2.f * uc, S, Q));
    }
    __shared__ float sh[256], sh2[256];
    sh[t] = s; sh2[t] = s2;
    __syncthreads();
    if (t < C) {
        float S = sh[t], S2 = sh2[t];
        #pragma unroll
        for (int gg = 1; gg < G; gg++) { S += sh[gg * C + t]; S2 += sh2[gg * C + t]; }
        g_part[blockIdx.x * (2 * C) + t] = S;
        g_part[blockIdx.x * (2 * C) + C + t] = S2;
    }
}

template <int C>
__global__ void fin_k(const float* __restrict__ gamma, const float* __restrict__ beta) {
    int c = threadIdx.x;
    float S = 0.f, S2 = 0.f;
    for (int bk = 0; bk < STATS_BLOCKS; bk++) {
        S += g_part[bk * 2 * C + c];
        S2 += g_part[bk * 2 * C + C + c];
    }
    const float inv = 1.f / (float)EDG;
    float mu = S * inv;
    float var = S2 * inv - mu * mu;
    float sc = gamma[c] * rsqrtf(var + 1e-5f);
    g_scale[c] = sc;
    g_shift[c] = beta[c] - mu * sc;
}

// ---------------- finish: h = leaky(scale*(u + vmax/vmin) + shift) -----------
template <int C>
__global__ void finish_k() {
    int gid = blockIdx.x * 256 + threadIdx.x;    // NPTS*C
    int c = gid & (C - 1);
    float sc = g_scale[c];
    float vm = (sc >= 0.f) ? g_vmax[gid] : g_vmin[gid];
    float M = g_u[gid] + vm;
    float* out = (C == 64) ? (float*)g_h0 : (float*)g_h1;
    out[gid] = leaky(fmaf(M, sc, g_shift[c]));
}

// ---------------- attention gate + softmax -----------------------------------
__global__ void gate_k(const float* __restrict__ Wg, const float* __restrict__ bg) {
    int gt = blockIdx.x * 256 + threadIdx.x;
    int r = gt >> 5, lane = gt & 31;
    if (r >= NPTS) return;
    const float* h = g_h1 + (size_t)r * 256;
    float s = 0.f;
    #pragma unroll
    for (int q = 0; q < 8; q++) {
        int d = lane + (q << 5);
        s = fmaf(h[d], Wg[d], s);
    }
    #pragma unroll
    for (int o = 16; o; o >>= 1) s += __shfl_down_sync(FULLM, s, o);
    if (lane == 0) {
        float gg = s + bg[0];
        g_gate[r] = gg > 0.f ? gg : 0.f;
    }
}

__global__ void softmax_k() {
    int b = blockIdx.x, t = threadIdx.x;
    __shared__ float sh[256];
    const float* gp = g_gate + (b << 12);
    float* ap = g_alpha + (b << 12);
    float mx = -FINF;
    for (int s = 0; s < 16; s++) mx = fmaxf(mx, gp[t + (s << 8)]);
    sh[t] = mx; __syncthreads();
    for (int o = 128; o; o >>= 1) { if (t < o) sh[t] = fmaxf(sh[t], sh[t + o]); __syncthreads(); }
    float M = sh[0];
    __syncthreads();
    float sum = 0.f;
    for (int s = 0; s < 16; s++) {
        int j = t + (s << 8);
        float e = expf(gp[j] - M);
        ap[j] = e;
        sum += e;
    }
    sh[t] = sum; __syncthreads();
    for (int o = 128; o; o >>= 1) { if (t < o) sh[t] += sh[t + o]; __syncthreads(); }
    float inv = 1.f / sh[0];
    for (int s = 0; s < 16; s++) ap[t + (s << 8)] *= inv;
}

// ---------------- fused feat GEMM + weighted pooling --------------------------
__global__ __launch_bounds__(256) void pool_k(const float* __restrict__ Wf,
                                              const float* __restrict__ bf) {
    int b = blockIdx.x;
    int t = threadIdx.x;
    int ch = blockIdx.y * 256 + t;
    int slab = blockIdx.z;
    __shared__ float hr[16][256];
    __shared__ float al[16];
    float acc = 0.f;
    float bfc = bf[ch];
    for (int gidx = 0; gidx < 8; gidx++) {
        int nb = (slab << 7) + (gidx << 4);
        __syncthreads();
        #pragma unroll
        for (int s = 0; s < 16; s++)
            hr[s][t] = g_h1[((size_t)(b << 12) + nb + s) * 256 + t];
        if (t < 16) al[t] = g_alpha[(b << 12) + nb + t];
        __syncthreads();
        float sacc[16];
        #pragma unroll
        for (int r = 0; r < 16; r++) sacc[r] = bfc;
        #pragma unroll 4
        for (int d = 0; d < 256; d += 4) {
            float w0 = Wf[(d + 0) * 512 + ch];
            float w1 = Wf[(d + 1) * 512 + ch];
            float w2 = Wf[(d + 2) * 512 + ch];
            float w3 = Wf[(d + 3) * 512 + ch];
            #pragma unroll
            for (int r = 0; r < 16; r++) {
                float4 hv = *(const float4*)&hr[r][d];
                sacc[r] = fmaf(hv.x, w0, fmaf(hv.y, w1, fmaf(hv.z, w2, fmaf(hv.w, w3, sacc[r]))));
            }
        }
        #pragma unroll
        for (int r = 0; r < 16; r++) {
            float f = sacc[r] > 0.f ? sacc[r] : 0.f;
            acc = fmaf(al[r], f, acc);
        }
    }
    g_pool[((slab << 2) + b) * 512 + ch] = acc;
}

__global__ void poolred_k() {
    int gid = blockIdx.x * 256 + threadIdx.x;  // BB*512
    if (gid >= BB * 512) return;
    int b = gid >> 9, ch = gid & 511;
    float s = 0.f;
    for (int sl = 0; sl < 32; sl++) s += g_pool[((sl << 2) + b) * 512 + ch];
    g_pooled[gid] = s;
}

__global__ void final_k(const float* __restrict__ Wl, const float* __restrict__ bl,
                        float* __restrict__ out) {
    int b = blockIdx.x, o = threadIdx.x;
    const float* p = g_pooled + b * 512;
    float s = bl[o];
    #pragma unroll 8
    for (int f = 0; f < 512; f++) s = fmaf(p[f], Wl[f * 256 + o], s);
    out[b * 256 + o] = s;
}

// ---------------- launch ------------------------------------------------------
extern "C" void kernel_launch(void* const* d_in, const int* in_sizes, int n_in,
                              void* d_out, int out_size) {
    (void)in_sizes; (void)n_in; (void)out_size;
    const float* x   = (const float*)d_in[0];
    const float* Wt0 = (const float*)d_in[1];
    const float* Wp0 = (const float*)d_in[3];
    const float* g0  = (const float*)d_in[5];
    const float* be0 = (const float*)d_in[6];
    const float* Wt1 = (const float*)d_in[7];
    const float* Wp1 = (const float*)d_in[9];
    const float* g1  = (const float*)d_in[11];
    const float* be1 = (const float*)d_in[12];
    const float* Wg  = (const float*)d_in[13];
    const float* bg  = (const float*)d_in[14];
    const float* Wf  = (const float*)d_in[15];
    const float* bf  = (const float*)d_in[16];
    const float* Wl  = (const float*)d_in[17];
    const float* bl  = (const float*)d_in[18];
    float* out = (float*)d_out;

    // ---- layer 0 ----
    prep_k<<<65, 256>>>(Wt0, Wp0, Wt1, Wp1);
    pack3_k<<<64, 256>>>(x);
    uv0_k<<<NPTS * 64 / 256, 256>>>(x, Wt0);
    knn0_k<<<NPTS / 8, 256>>>();
    gather_k<64><<<STATS_BLOCKS, 256>>>();
    fin_k<64><<<1, 64>>>(g0, be0);
    finish_k<64><<<NPTS * 64 / 256, 256>>>();

    // ---- layer 1 ----
    norms64_k<<<NPTS * 32 / 256, 256>>>();
    gemm16_k<<<NPTS / 16, 256>>>(Wt1);
    dist_gemm_k<<<dim3(2080, BB), 256>>>();
    knn1_k<<<NPTS / 8, 256>>>();
    gather_k<256><<<STATS_BLOCKS, 256>>>();
    fin_k<256><<<1, 256>>>(g1, be1);
    finish_k<256><<<NPTS * 256 / 256, 256>>>();

    // ---- attention pooling + final linear ----
    gate_k<<<NPTS * 32 / 256, 256>>>(Wg, bg);
    softmax_k<<<BB, 256>>>();
    pool_k<<<dim3(BB, 2, 32), 256>>>(Wf, bf);
    poolred_k<<<8, 256>>>();
    final_k<<<BB, 256>>>(Wl, bl, out);
}